// round 10
// baseline (speedup 1.0000x reference)
#include <cuda_runtime.h>
#include <cuda_fp16.h>
#include <math.h>
#include <stdint.h>

#define B_  2
#define S_  512
#define N_  20000
#define D_  384
#define H_  3
#define C_  128
#define F_  384
#define E_  320000
#define DG_ 128
#define BN_ (B_*N_)
#define BE_ (B_*E_)

#define NW_      768
#define KV_XP    1024                  // 2-term virtual K for xp
#define NCH_XP   32
#define KPAD_    20480
#define LDA_PJ   (2*KPAD_)             // 40960
#define KV_PJ    (2*KPAD_)             // 40960 (2-term)
#define NSPLIT_PJ 16
#define KCHUNK_PJ (KV_PJ/NSPLIT_PJ)    // 2560
#define NCH_PJ   (KCHUNK_PJ/32)        // 80
#define STG_A    10240                 // 128*40*2
#define STG_B    8704                  // 32*136*2
#define STG_SZ   (STG_A+STG_B)         // 18944
#define SMEM_MMA (4*STG_SZ)            // 75776

// ---------------- device scratch ----------------
__device__ __align__(16) __half g_Y2[512*NW_];                 // fp16, single
__device__ __align__(16) __half g_Wq2[(size_t)N_*1024];        // [20000, hi|lo 1024]
__device__ __align__(16) __half g_Wp2[(size_t)S_*LDA_PJ];      // [512, hi|lo 40960]
__device__ __align__(16) __half g_gat2[(size_t)KPAD_*NW_];     // fp16 single; pad rows stay 0
__device__ __align__(16) __half g_xp[(size_t)BN_*F_];          // fp16 now
__device__ float g_uvw[3*F_];
__device__ float g_asrc[BN_*H_];
__device__ float g_adst[BN_*H_];
__device__ float g_rden[BN_*H_];
__device__ int   g_off[BN_+1];
__device__ int   g_cnt[BN_];
__device__ int   g_cur[BN_];
__device__ int   g_esrc[BE_];
__device__ float g_tmp[B_*S_*F_];

__device__ __forceinline__ float lrelu(float x){ return x > 0.f ? x : 0.2f*x; }
__device__ __forceinline__ unsigned su(const void* p){
    return (unsigned)__cvta_generic_to_shared(p);
}
__device__ __forceinline__ void cpa16(unsigned dst, const void* src, bool pred){
    int sz = pred ? 16 : 0;
    asm volatile("cp.async.cg.shared.global [%0], [%1], 16, %2;\n"
                 :: "r"(dst), "l"(src), "r"(sz));
}
__device__ __forceinline__ void ldsm4(unsigned addr, unsigned &r0, unsigned &r1, unsigned &r2, unsigned &r3){
    asm volatile("ldmatrix.sync.aligned.m8n8.x4.shared.b16 {%0,%1,%2,%3}, [%4];\n"
                 : "=r"(r0),"=r"(r1),"=r"(r2),"=r"(r3) : "r"(addr));
}
__device__ __forceinline__ void ldsm4t(unsigned addr, unsigned &r0, unsigned &r1, unsigned &r2, unsigned &r3){
    asm volatile("ldmatrix.sync.aligned.m8n8.x4.trans.shared.b16 {%0,%1,%2,%3}, [%4];\n"
                 : "=r"(r0),"=r"(r1),"=r"(r2),"=r"(r3) : "r"(addr));
}
__device__ __forceinline__ void mma16816(float* c, const unsigned* a, const unsigned* b){
    asm volatile("mma.sync.aligned.m16n8k16.row.col.f32.f16.f16.f32 "
                 "{%0,%1,%2,%3},{%4,%5,%6,%7},{%8,%9},{%0,%1,%2,%3};\n"
                 : "+f"(c[0]),"+f"(c[1]),"+f"(c[2]),"+f"(c[3])
                 : "r"(a[0]),"r"(a[1]),"r"(a[2]),"r"(a[3]),"r"(b[0]),"r"(b[1]));
}

// ---------------- small kernels ----------------
__global__ void k_zero(){
    int i = blockIdx.x*blockDim.x + threadIdx.x;
    if (i < BN_){ g_cnt[i] = 0; g_cur[i] = 0; }
}
__global__ void k_uvw(const float* __restrict__ Wlin, const float* __restrict__ Wm,
                      const float* __restrict__ bm){
    int f = blockIdx.x*blockDim.x + threadIdx.x;
    if (f >= F_) return;
    float u=0.f, v=0.f, w=0.f;
    for (int d = 0; d < D_; d++){
        float wl = Wlin[f*D_ + d];
        u += wl*Wm[d]; v += wl*bm[d]; w += wl;
    }
    g_uvw[f]=u; g_uvw[F_+f]=v; g_uvw[2*F_+f]=w;
}
__global__ void k_tmpinit(const float* __restrict__ bproj){
    int i = blockIdx.x*blockDim.x + threadIdx.x;
    if (i >= B_*S_*F_) return;
    g_tmp[i] = bproj[(i / F_) % S_];
}

// ---------------- vectorized hi/lo weight splits (fp16 2-term) ----------------
__global__ void k_split_wq2(const float* __restrict__ Wq){
    int i4 = blockIdx.x*blockDim.x + threadIdx.x;
    if (i4 >= N_*(S_/4)) return;
    int m = i4 >> 7, k = (i4 & 127) << 2;
    float4 x = *(const float4*)(Wq + (size_t)m*S_ + k);
    float xs[4] = {x.x, x.y, x.z, x.w};
    union { __half b[4]; uint2 u; } hh, ll;
    #pragma unroll
    for (int j = 0; j < 4; j++){
        __half h = __float2half_rn(xs[j]);
        hh.b[j] = h;
        ll.b[j] = __float2half_rn(xs[j] - __half2float(h));
    }
    size_t base = (size_t)m*1024;
    *(uint2*)&g_Wq2[base + k]       = hh.u;
    *(uint2*)&g_Wq2[base + 512 + k] = ll.u;
}
__global__ void k_split_wp2(const float* __restrict__ Wproj){
    int i4 = blockIdx.x*blockDim.x + threadIdx.x;     // 512 * 5120
    if (i4 >= S_*(KPAD_/4)) return;
    int m = i4 / (KPAD_/4), k = (i4 % (KPAD_/4)) << 2;
    float4 x = (k < N_) ? *(const float4*)(Wproj + (size_t)m*N_ + k)
                        : make_float4(0.f,0.f,0.f,0.f);
    float xs[4] = {x.x, x.y, x.z, x.w};
    union { __half b[4]; uint2 u; } hh, ll;
    #pragma unroll
    for (int j = 0; j < 4; j++){
        __half h = __float2half_rn(xs[j]);
        hh.b[j] = h;
        ll.b[j] = __float2half_rn(xs[j] - __half2float(h));
    }
    size_t base = (size_t)m*LDA_PJ;
    *(uint2*)&g_Wp2[base + k]         = hh.u;
    *(uint2*)&g_Wp2[base + KPAD_ + k] = ll.u;
}

// ---------------- fp32 tiled GEMM (small), C = A @ Bm^T ----------------
__global__ void k_gemm_bt(const float* __restrict__ A, int strideA,
                          const float* __restrict__ Bm,
                          float* __restrict__ C, int strideC,
                          int K, int Ncol, const float* __restrict__ bias_col,
                          __half* __restrict__ Ysplit){
    const float* Ab = A + blockIdx.z * strideA;
    int m0 = blockIdx.y*64, n0 = blockIdx.x*64;
    __shared__ float As[16][64];
    __shared__ float Bs[16][64];
    int tid = threadIdx.x;
    int tm = tid >> 4, tn = tid & 15;
    int lrow = tid >> 2, lcol = (tid & 3)*4;
    float acc[4][4] = {};
    for (int k0 = 0; k0 < K; k0 += 16){
        float4 av = *(const float4*)(Ab + (m0+lrow)*K + k0 + lcol);
        As[lcol+0][lrow]=av.x; As[lcol+1][lrow]=av.y; As[lcol+2][lrow]=av.z; As[lcol+3][lrow]=av.w;
        float4 bv = *(const float4*)(Bm + (n0+lrow)*K + k0 + lcol);
        Bs[lcol+0][lrow]=bv.x; Bs[lcol+1][lrow]=bv.y; Bs[lcol+2][lrow]=bv.z; Bs[lcol+3][lrow]=bv.w;
        __syncthreads();
        #pragma unroll
        for (int kk = 0; kk < 16; kk++){
            float4 a4 = *(const float4*)&As[kk][tm*4];
            float4 b4 = *(const float4*)&Bs[kk][tn*4];
            float ar[4]={a4.x,a4.y,a4.z,a4.w}, br[4]={b4.x,b4.y,b4.z,b4.w};
            #pragma unroll
            for (int i=0;i<4;i++)
                #pragma unroll
                for (int j=0;j<4;j++) acc[i][j]=fmaf(ar[i],br[j],acc[i][j]);
        }
        __syncthreads();
    }
    #pragma unroll
    for (int i=0;i<4;i++){
        int row = m0 + tm*4 + i;
        #pragma unroll
        for (int j=0;j<4;j++){
            int col = n0 + tn*4 + j;
            float v = acc[i][j];
            if (Ysplit){
                int gc = blockIdx.z*384 + col;
                Ysplit[(size_t)row*NW_ + gc] = __float2half_rn(v);
            } else {
                v += bias_col[col];
                (C + blockIdx.z*strideC)[row*Ncol + col] = v;
            }
        }
    }
}

// ---------------- fp16 mma.sync GEMM, 128x128 CTA, 64x64 warps, 4-stage, frag dbuf ----
template<int EPI>
__global__ __launch_bounds__(128, 2)
void k_mma(const __half* __restrict__ A, int lda, int M, int TA,
           const __half* __restrict__ Bm, int TB,
           int kchunk, int nchunks,
           const float* __restrict__ bq, const float* __restrict__ mask)
{
    extern __shared__ __align__(16) char smem[];
    uint32_t sbase = su(smem);

    const int tid = threadIdx.x, lane = tid & 31, wid = tid >> 5;
    const int wm = wid & 1, wn = wid >> 1;
    const int m0 = blockIdx.y*128, n0 = blockIdx.x*128;
    const int kbeg = blockIdx.z * kchunk;
    const int lrow = lane & 15, lhi = lane >> 4;

    auto load_stage = [&](int s, int c){
        int kv = kbeg + c*32;
        int ka = (kv >= TA) ? kv - TA : kv;
        int kb = (kv >= TB) ? kv - TB : kv;
        uint32_t ab = sbase + s*STG_SZ;
        uint32_t bb = ab + STG_A;
        #pragma unroll
        for (int i = tid; i < 512; i += 128){
            int row = i >> 2, seg = i & 3;
            int gr = m0 + row;
            const void* src = A + (size_t)(gr < M ? gr : M-1)*lda + ka + seg*8;
            cpa16(ab + (uint32_t)(row*80 + seg*16), src, gr < M);
        }
        #pragma unroll
        for (int i = tid; i < 512; i += 128){
            int row = i >> 4, seg = i & 15;
            const void* src = Bm + (size_t)(kb + row)*NW_ + n0 + seg*8;
            cpa16(bb + (uint32_t)(row*272 + seg*16), src, true);
        }
    };

    unsigned afr[2][4][4], bfr[2][8][2];
    auto ldfr = [&](int s, int kk, int buf){
        uint32_t ab = sbase + s*STG_SZ;
        uint32_t bb = ab + STG_A;
        int k0 = kk*16;
        #pragma unroll
        for (int mi = 0; mi < 4; ++mi){
            unsigned addr = ab + (uint32_t)((wm*64 + mi*16 + lrow)*80 + (k0 + lhi*8)*2);
            ldsm4(addr, afr[buf][mi][0], afr[buf][mi][1], afr[buf][mi][2], afr[buf][mi][3]);
        }
        #pragma unroll
        for (int nt = 0; nt < 4; ++nt){
            unsigned addr = bb + (uint32_t)((k0 + lrow)*272 + (wn*64 + nt*16 + lhi*8)*2);
            unsigned r0,r1,r2,r3;
            ldsm4t(addr, r0,r1,r2,r3);
            bfr[buf][nt*2  ][0]=r0; bfr[buf][nt*2  ][1]=r1;
            bfr[buf][nt*2+1][0]=r2; bfr[buf][nt*2+1][1]=r3;
        }
    };

    float acc[4][8][4] = {};

    #pragma unroll
    for (int s = 0; s < 3; s++){
        load_stage(s, s);
        asm volatile("cp.async.commit_group;");
    }
    asm volatile("cp.async.wait_group 2;");
    __syncthreads();
    ldfr(0, 0, 0);

    for (int c = 0; c < nchunks; ++c){
        int s = c & 3;
        ldfr(s, 1, 1);
        #pragma unroll
        for (int mi = 0; mi < 4; ++mi)
            #pragma unroll
            for (int ni = 0; ni < 8; ++ni)
                mma16816(acc[mi][ni], afr[0][mi], bfr[0][ni]);
        if (c + 3 < nchunks) load_stage((c+3)&3, c+3);
        asm volatile("cp.async.commit_group;");
        if (c + 1 < nchunks){
            asm volatile("cp.async.wait_group 2;");
            __syncthreads();
            ldfr((c+1)&3, 0, 0);
        }
        #pragma unroll
        for (int mi = 0; mi < 4; ++mi)
            #pragma unroll
            for (int ni = 0; ni < 8; ++ni)
                mma16816(acc[mi][ni], afr[1][mi], bfr[1][ni]);
    }

    // epilogue
    int g = lane >> 2, tig = lane & 3;
    #pragma unroll
    for (int mi = 0; mi < 4; ++mi){
        #pragma unroll
        for (int half = 0; half < 2; ++half){
            int row = m0 + wm*64 + mi*16 + g + half*8;
            if (row >= M) continue;
            float bqv = 0.f, mv0 = 0.f, mv1 = 0.f;
            if constexpr (EPI == 0){
                bqv = bq[row];
                mv0 = mask[row];
                mv1 = mask[N_ + row];
            }
            #pragma unroll
            for (int ni = 0; ni < 8; ++ni){
                int col = n0 + wn*64 + ni*8 + tig*2;
                int bb2 = col >= 384;
                int f = col - bb2*384;
                float v0 = acc[mi][ni][half*2+0];
                float v1 = acc[mi][ni][half*2+1];
                if constexpr (EPI == 0){
                    float mv = bb2 ? mv1 : mv0;
                    v0 += bqv*g_uvw[2*F_+f]   + mv*g_uvw[f]   + g_uvw[F_+f];
                    v1 += bqv*g_uvw[2*F_+f+1] + mv*g_uvw[f+1] + g_uvw[F_+f+1];
                    *(__half2*)&g_xp[((size_t)bb2*N_ + row)*F_ + f] = __floats2half2_rn(v0, v1);
                } else {
                    float* dst = &g_tmp[((size_t)bb2*S_ + row)*F_ + f];
                    atomicAdd(&dst[0], v0);
                    atomicAdd(&dst[1], v1);
                }
            }
        }
    }
}

// ---------------- attention scalars (fp16 xp reads) ----------------
__global__ void k_attn(const float* __restrict__ att_src, const float* __restrict__ att_dst){
    int gw = (blockIdx.x*blockDim.x + threadIdx.x) >> 5;
    if (gw >= BN_*H_) return;
    int lane = threadIdx.x & 31;
    int n = gw / H_, h = gw % H_;
    const __half* xrow = g_xp + (size_t)n*F_ + h*C_;
    __half2 h0 = ((const __half2*)xrow)[lane*2];
    __half2 h1 = ((const __half2*)xrow)[lane*2+1];
    float2 f0 = __half22float2(h0), f1 = __half22float2(h1);
    int c = lane*4;
    float s1 = f0.x*att_src[h*C_+c]   + f0.y*att_src[h*C_+c+1]
             + f1.x*att_src[h*C_+c+2] + f1.y*att_src[h*C_+c+3];
    float s2 = f0.x*att_dst[h*C_+c]   + f0.y*att_dst[h*C_+c+1]
             + f1.x*att_dst[h*C_+c+2] + f1.y*att_dst[h*C_+c+3];
    #pragma unroll
    for (int o = 16; o; o >>= 1){
        s1 += __shfl_xor_sync(0xffffffffu, s1, o);
        s2 += __shfl_xor_sync(0xffffffffu, s2, o);
    }
    if (lane == 0){ g_asrc[n*H_+h] = s1; g_adst[n*H_+h] = s2; }
}

// ---------------- CSR ----------------
__global__ void k_count(const int* __restrict__ ei){
    int e = blockIdx.x*blockDim.x + threadIdx.x;
    if (e >= BE_) return;
    int b = e / E_, j = e - b*E_;
    atomicAdd(&g_cnt[ei[E_ + j] + b*N_], 1);
}
__global__ void k_scan(){
    __shared__ int ssum[1024];
    int tid = threadIdx.x;
    const int CH = (BN_ + 1023)/1024;
    int base = tid*CH, s = 0;
    for (int i = 0; i < CH; i++){ int idx = base+i; if (idx < BN_) s += g_cnt[idx]; }
    ssum[tid] = s;
    __syncthreads();
    for (int off = 1; off < 1024; off <<= 1){
        int v = (tid >= off) ? ssum[tid-off] : 0;
        __syncthreads();
        ssum[tid] += v;
        __syncthreads();
    }
    int run = ssum[tid] - s;
    for (int i = 0; i < CH; i++){
        int idx = base+i;
        if (idx < BN_){ g_off[idx] = run; run += g_cnt[idx]; }
    }
    if (tid == 1023) g_off[BN_] = ssum[1023];
}
__global__ void k_scatter(const int* __restrict__ ei){
    int e = blockIdx.x*blockDim.x + threadIdx.x;
    if (e >= BE_) return;
    int b = e / E_, j = e - b*E_;
    int src = ei[j] + b*N_;
    int dst = ei[E_ + j] + b*N_;
    int pos = g_off[dst] + atomicAdd(&g_cur[dst], 1);
    g_esrc[pos] = src;
}

// ---------------- one-pass softmax denominators (shift-invariant, scores are tiny) ----
__global__ void k_softmax(){
    int gw = (blockIdx.x*blockDim.x + threadIdx.x) >> 5;
    if (gw >= BN_) return;
    int lane = threadIdx.x & 31, n = gw;
    float ad0=g_adst[n*3+0], ad1=g_adst[n*3+1], ad2=g_adst[n*3+2];
    int beg=g_off[n], end=g_off[n+1];
    float s0=0.f, s1=0.f, s2=0.f;
    for (int i = beg+lane; i < end; i += 32){
        int s = g_esrc[i];
        s0 += __expf(lrelu(g_asrc[s*3+0]+ad0));
        s1 += __expf(lrelu(g_asrc[s*3+1]+ad1));
        s2 += __expf(lrelu(g_asrc[s*3+2]+ad2));
    }
    #pragma unroll
    for (int o = 16; o; o >>= 1){
        s0 += __shfl_xor_sync(0xffffffffu, s0, o);
        s1 += __shfl_xor_sync(0xffffffffu, s1, o);
        s2 += __shfl_xor_sync(0xffffffffu, s2, o);
    }
    if (lane == 0){
        s0 += __expf(lrelu(g_asrc[n*3+0]+ad0));
        s1 += __expf(lrelu(g_asrc[n*3+1]+ad1));
        s2 += __expf(lrelu(g_asrc[n*3+2]+ad2));
        g_rden[n*3+0]=1.f/s0; g_rden[n*3+1]=1.f/s1; g_rden[n*3+2]=1.f/s2;
    }
}

// ---------------- aggregation: inline alpha (no max shift), fp16 gathers ----------
__global__ void k_aggregate(const float* __restrict__ bias_gat){
    int n = blockIdx.x;
    int tid = threadIdx.x;      // 0..95, covers cols [tid*4, tid*4+4)
    int h = tid >> 5;
    int beg = g_off[n], end = g_off[n+1];
    float ad = g_adst[n*3+h];
    float rd = g_rden[n*3+h];
    const uint2* xp2 = (const uint2*)g_xp;    // 4 halves per uint2, 96 per row
    float4 acc = make_float4(0.f,0.f,0.f,0.f);
    for (int i = beg; i < end; i++){
        int s = g_esrc[i];
        float al = __expf(lrelu(g_asrc[s*3+h] + ad)) * rd;
        uint2 raw = xp2[(size_t)s*96 + tid];
        float2 v0 = __half22float2(*(const __half2*)&raw.x);
        float2 v1 = __half22float2(*(const __half2*)&raw.y);
        acc.x = fmaf(v0.x, al, acc.x); acc.y = fmaf(v0.y, al, acc.y);
        acc.z = fmaf(v1.x, al, acc.z); acc.w = fmaf(v1.y, al, acc.w);
    }
    float als = __expf(lrelu(g_asrc[n*3+h] + ad)) * rd;
    {
        uint2 raw = xp2[(size_t)n*96 + tid];
        float2 v0 = __half22float2(*(const __half2*)&raw.x);
        float2 v1 = __half22float2(*(const __half2*)&raw.y);
        acc.x = fmaf(v0.x, als, acc.x); acc.y = fmaf(v0.y, als, acc.y);
        acc.z = fmaf(v1.x, als, acc.z); acc.w = fmaf(v1.y, als, acc.w);
    }
    float4 bg = ((const float4*)bias_gat)[tid];
    acc.x += bg.x; acc.y += bg.y; acc.z += bg.z; acc.w += bg.w;

    int b = n / N_;
    int k = n - b*N_;
    int col = b*384 + tid*4;
    union { __half bv[4]; uint2 u; } hh;
    hh.bv[0] = __float2half_rn(acc.x);
    hh.bv[1] = __float2half_rn(acc.y);
    hh.bv[2] = __float2half_rn(acc.z);
    hh.bv[3] = __float2half_rn(acc.w);
    *(uint2*)&g_gat2[(size_t)k*NW_ + col] = hh.u;
}

// ---------------- host ----------------
extern "C" void kernel_launch(void* const* d_in, const int* in_sizes, int n_in,
                              void* d_out, int out_size){
    const float* x_enc    = (const float*)d_in[0];
    const float* mask     = (const float*)d_in[1];
    const int*   ei       = (const int*)  d_in[2];
    const float* Wq       = (const float*)d_in[3];
    const float* bq       = (const float*)d_in[4];
    const float* Wm       = (const float*)d_in[5];
    const float* bm       = (const float*)d_in[6];
    const float* Wlin     = (const float*)d_in[7];
    const float* att_src  = (const float*)d_in[8];
    const float* att_dst  = (const float*)d_in[9];
    const float* bias_gat = (const float*)d_in[10];
    const float* Wproj    = (const float*)d_in[11];
    const float* bproj    = (const float*)d_in[12];
    const float* Wtemp    = (const float*)d_in[13];
    const float* btemp    = (const float*)d_in[14];
    float* out = (float*)d_out;

    void *pY2=0, *pWq2=0, *pWp2=0, *pG2=0, *pTmp=0;
    cudaGetSymbolAddress(&pY2,  g_Y2);
    cudaGetSymbolAddress(&pWq2, g_Wq2);
    cudaGetSymbolAddress(&pWp2, g_Wp2);
    cudaGetSymbolAddress(&pG2,  g_gat2);
    cudaGetSymbolAddress(&pTmp, g_tmp);

    cudaFuncSetAttribute(k_mma<0>, cudaFuncAttributeMaxDynamicSharedMemorySize, SMEM_MMA);
    cudaFuncSetAttribute(k_mma<1>, cudaFuncAttributeMaxDynamicSharedMemorySize, SMEM_MMA);

    k_uvw<<<3, 128>>>(Wlin, Wm, bm);
    k_gemm_bt<<<dim3(F_/64, S_/64, B_), 256>>>(
        x_enc, S_*D_, Wlin, nullptr, 0, D_, F_, nullptr, (__half*)pY2);
    k_split_wq2<<<(N_*(S_/4) + 255)/256, 256>>>(Wq);
    k_mma<0><<<dim3(NW_/128, (N_ + 127)/128, 1), 128, SMEM_MMA>>>(
        (const __half*)pWq2, 1024, N_, 1024,
        (const __half*)pY2, 512,
        KV_XP, NCH_XP, bq, mask);

    k_zero<<<(BN_ + 255)/256, 256>>>();
    k_count<<<(BE_ + 255)/256, 256>>>(ei);
    k_scan<<<1, 1024>>>();
    k_scatter<<<(BE_ + 255)/256, 256>>>(ei);

    k_attn<<<(BN_*H_*32 + 127)/128, 128>>>(att_src, att_dst);
    k_softmax<<<(BN_*32 + 127)/128, 128>>>();
    k_aggregate<<<BN_, 96>>>(bias_gat);

    k_split_wp2<<<(S_*(KPAD_/4) + 255)/256, 256>>>(Wproj);
    k_tmpinit<<<(B_*S_*F_ + 255)/256, 256>>>(bproj);
    k_mma<1><<<dim3(NW_/128, S_/128, NSPLIT_PJ), 128, SMEM_MMA>>>(
        (const __half*)pWp2, LDA_PJ, S_, LDA_PJ,
        (const __half*)pG2, KPAD_,
        KCHUNK_PJ, NCH_PJ, nullptr, nullptr);

    k_gemm_bt<<<dim3(DG_/64, (B_*S_)/64, 1), 256>>>(
        (const float*)pTmp, 0, Wtemp, out, 0, F_, DG_, btemp, nullptr);
}

// round 11
// speedup vs baseline: 1.0010x; 1.0010x over previous
#include <cuda_runtime.h>
#include <cuda_fp16.h>
#include <math.h>
#include <stdint.h>

#define B_  2
#define S_  512
#define N_  20000
#define D_  384
#define H_  3
#define C_  128
#define F_  384
#define E_  320000
#define DG_ 128
#define BN_ (B_*N_)
#define BE_ (B_*E_)

#define NW_      768
#define KV_XP    1024                  // 2-term virtual K for xp
#define NCH_XP   32
#define KPAD_    20480
#define LDA_PJ   (2*KPAD_)             // 40960
#define KV_PJ    (2*KPAD_)             // 40960 (2-term)
#define NSPLIT_PJ 32
#define KCHUNK_PJ (KV_PJ/NSPLIT_PJ)    // 1280
#define NCH_PJ   (KCHUNK_PJ/32)        // 40
#define STG_A    10240                 // 128*40*2
#define STG_B    8704                  // 32*136*2
#define STG_SZ   (STG_A+STG_B)         // 18944
#define SMEM_MMA (4*STG_SZ)            // 75776

// ---------------- device scratch ----------------
__device__ __align__(16) __half g_Y2[512*NW_];                 // fp16, single
__device__ __align__(16) __half g_Wq2[(size_t)N_*1024];        // [20000, hi|lo 1024]
__device__ __align__(16) __half g_Wp2[(size_t)S_*LDA_PJ];      // [512, hi|lo 40960]
__device__ __align__(16) __half g_gat2[(size_t)KPAD_*NW_];     // fp16 single; pad rows stay 0
__device__ __align__(16) __half g_xp[(size_t)BN_*F_];          // fp16
__device__ float g_uvw[3*F_];
__device__ float g_asrc[BN_*H_];
__device__ float g_adst[BN_*H_];
__device__ int   g_off[BN_+1];
__device__ int   g_cnt[BN_];
__device__ int   g_cur[BN_];
__device__ int   g_esrc[BE_];
__device__ float g_tmp[B_*S_*F_];

__device__ __forceinline__ float lrelu(float x){ return x > 0.f ? x : 0.2f*x; }
__device__ __forceinline__ unsigned su(const void* p){
    return (unsigned)__cvta_generic_to_shared(p);
}
__device__ __forceinline__ void cpa16(unsigned dst, const void* src, bool pred){
    int sz = pred ? 16 : 0;
    asm volatile("cp.async.cg.shared.global [%0], [%1], 16, %2;\n"
                 :: "r"(dst), "l"(src), "r"(sz));
}
__device__ __forceinline__ void ldsm4(unsigned addr, unsigned &r0, unsigned &r1, unsigned &r2, unsigned &r3){
    asm volatile("ldmatrix.sync.aligned.m8n8.x4.shared.b16 {%0,%1,%2,%3}, [%4];\n"
                 : "=r"(r0),"=r"(r1),"=r"(r2),"=r"(r3) : "r"(addr));
}
__device__ __forceinline__ void ldsm4t(unsigned addr, unsigned &r0, unsigned &r1, unsigned &r2, unsigned &r3){
    asm volatile("ldmatrix.sync.aligned.m8n8.x4.trans.shared.b16 {%0,%1,%2,%3}, [%4];\n"
                 : "=r"(r0),"=r"(r1),"=r"(r2),"=r"(r3) : "r"(addr));
}
__device__ __forceinline__ void mma16816(float* c, const unsigned* a, const unsigned* b){
    asm volatile("mma.sync.aligned.m16n8k16.row.col.f32.f16.f16.f32 "
                 "{%0,%1,%2,%3},{%4,%5,%6,%7},{%8,%9},{%0,%1,%2,%3};\n"
                 : "+f"(c[0]),"+f"(c[1]),"+f"(c[2]),"+f"(c[3])
                 : "r"(a[0]),"r"(a[1]),"r"(a[2]),"r"(a[3]),"r"(b[0]),"r"(b[1]));
}

// ---------------- small kernels ----------------
__global__ void k_zero(){
    int i = blockIdx.x*blockDim.x + threadIdx.x;
    if (i < BN_){ g_cnt[i] = 0; g_cur[i] = 0; }
}
__global__ void k_uvw(const float* __restrict__ Wlin, const float* __restrict__ Wm,
                      const float* __restrict__ bm){
    int f = blockIdx.x*blockDim.x + threadIdx.x;
    if (f >= F_) return;
    float u=0.f, v=0.f, w=0.f;
    for (int d = 0; d < D_; d++){
        float wl = Wlin[f*D_ + d];
        u += wl*Wm[d]; v += wl*bm[d]; w += wl;
    }
    g_uvw[f]=u; g_uvw[F_+f]=v; g_uvw[2*F_+f]=w;
}
__global__ void k_tmpinit(const float* __restrict__ bproj){
    int i = blockIdx.x*blockDim.x + threadIdx.x;
    if (i >= B_*S_*F_) return;
    g_tmp[i] = bproj[(i / F_) % S_];
}

// ---------------- vectorized hi/lo weight splits (fp16 2-term) ----------------
__global__ void k_split_wq2(const float* __restrict__ Wq){
    int i4 = blockIdx.x*blockDim.x + threadIdx.x;
    if (i4 >= N_*(S_/4)) return;
    int m = i4 >> 7, k = (i4 & 127) << 2;
    float4 x = *(const float4*)(Wq + (size_t)m*S_ + k);
    float xs[4] = {x.x, x.y, x.z, x.w};
    union { __half b[4]; uint2 u; } hh, ll;
    #pragma unroll
    for (int j = 0; j < 4; j++){
        __half h = __float2half_rn(xs[j]);
        hh.b[j] = h;
        ll.b[j] = __float2half_rn(xs[j] - __half2float(h));
    }
    size_t base = (size_t)m*1024;
    *(uint2*)&g_Wq2[base + k]       = hh.u;
    *(uint2*)&g_Wq2[base + 512 + k] = ll.u;
}
__global__ void k_split_wp2(const float* __restrict__ Wproj){
    int i4 = blockIdx.x*blockDim.x + threadIdx.x;     // 512 * 5120
    if (i4 >= S_*(KPAD_/4)) return;
    int m = i4 / (KPAD_/4), k = (i4 % (KPAD_/4)) << 2;
    float4 x = (k < N_) ? *(const float4*)(Wproj + (size_t)m*N_ + k)
                        : make_float4(0.f,0.f,0.f,0.f);
    float xs[4] = {x.x, x.y, x.z, x.w};
    union { __half b[4]; uint2 u; } hh, ll;
    #pragma unroll
    for (int j = 0; j < 4; j++){
        __half h = __float2half_rn(xs[j]);
        hh.b[j] = h;
        ll.b[j] = __float2half_rn(xs[j] - __half2float(h));
    }
    size_t base = (size_t)m*LDA_PJ;
    *(uint2*)&g_Wp2[base + k]         = hh.u;
    *(uint2*)&g_Wp2[base + KPAD_ + k] = ll.u;
}

// ---------------- fp32 tiled GEMM (small), C = A @ Bm^T ----------------
__global__ void k_gemm_bt(const float* __restrict__ A, int strideA,
                          const float* __restrict__ Bm,
                          float* __restrict__ C, int strideC,
                          int K, int Ncol, const float* __restrict__ bias_col,
                          __half* __restrict__ Ysplit){
    const float* Ab = A + blockIdx.z * strideA;
    int m0 = blockIdx.y*64, n0 = blockIdx.x*64;
    __shared__ float As[16][64];
    __shared__ float Bs[16][64];
    int tid = threadIdx.x;
    int tm = tid >> 4, tn = tid & 15;
    int lrow = tid >> 2, lcol = (tid & 3)*4;
    float acc[4][4] = {};
    for (int k0 = 0; k0 < K; k0 += 16){
        float4 av = *(const float4*)(Ab + (m0+lrow)*K + k0 + lcol);
        As[lcol+0][lrow]=av.x; As[lcol+1][lrow]=av.y; As[lcol+2][lrow]=av.z; As[lcol+3][lrow]=av.w;
        float4 bv = *(const float4*)(Bm + (n0+lrow)*K + k0 + lcol);
        Bs[lcol+0][lrow]=bv.x; Bs[lcol+1][lrow]=bv.y; Bs[lcol+2][lrow]=bv.z; Bs[lcol+3][lrow]=bv.w;
        __syncthreads();
        #pragma unroll
        for (int kk = 0; kk < 16; kk++){
            float4 a4 = *(const float4*)&As[kk][tm*4];
            float4 b4 = *(const float4*)&Bs[kk][tn*4];
            float ar[4]={a4.x,a4.y,a4.z,a4.w}, br[4]={b4.x,b4.y,b4.z,b4.w};
            #pragma unroll
            for (int i=0;i<4;i++)
                #pragma unroll
                for (int j=0;j<4;j++) acc[i][j]=fmaf(ar[i],br[j],acc[i][j]);
        }
        __syncthreads();
    }
    #pragma unroll
    for (int i=0;i<4;i++){
        int row = m0 + tm*4 + i;
        #pragma unroll
        for (int j=0;j<4;j++){
            int col = n0 + tn*4 + j;
            float v = acc[i][j];
            if (Ysplit){
                int gc = blockIdx.z*384 + col;
                Ysplit[(size_t)row*NW_ + gc] = __float2half_rn(v);
            } else {
                v += bias_col[col];
                (C + blockIdx.z*strideC)[row*Ncol + col] = v;
            }
        }
    }
}

// ---------------- fp16 mma.sync GEMM, 128x128 CTA, 64x64 warps, 4-stage, frag dbuf ----
template<int EPI>
__global__ __launch_bounds__(128, 2)
void k_mma(const __half* __restrict__ A, int lda, int M, int TA,
           const __half* __restrict__ Bm, int TB,
           int kchunk, int nchunks,
           const float* __restrict__ bq, const float* __restrict__ mask)
{
    extern __shared__ __align__(16) char smem[];
    uint32_t sbase = su(smem);

    const int tid = threadIdx.x, lane = tid & 31, wid = tid >> 5;
    const int wm = wid & 1, wn = wid >> 1;
    const int m0 = blockIdx.y*128, n0 = blockIdx.x*128;
    const int kbeg = blockIdx.z * kchunk;
    const int lrow = lane & 15, lhi = lane >> 4;

    auto load_stage = [&](int s, int c){
        int kv = kbeg + c*32;
        int ka = (kv >= TA) ? kv - TA : kv;
        int kb = (kv >= TB) ? kv - TB : kv;
        uint32_t ab = sbase + s*STG_SZ;
        uint32_t bb = ab + STG_A;
        #pragma unroll
        for (int i = tid; i < 512; i += 128){
            int row = i >> 2, seg = i & 3;
            int gr = m0 + row;
            const void* src = A + (size_t)(gr < M ? gr : M-1)*lda + ka + seg*8;
            cpa16(ab + (uint32_t)(row*80 + seg*16), src, gr < M);
        }
        #pragma unroll
        for (int i = tid; i < 512; i += 128){
            int row = i >> 4, seg = i & 15;
            const void* src = Bm + (size_t)(kb + row)*NW_ + n0 + seg*8;
            cpa16(bb + (uint32_t)(row*272 + seg*16), src, true);
        }
    };

    unsigned afr[2][4][4], bfr[2][8][2];
    auto ldfr = [&](int s, int kk, int buf){
        uint32_t ab = sbase + s*STG_SZ;
        uint32_t bb = ab + STG_A;
        int k0 = kk*16;
        #pragma unroll
        for (int mi = 0; mi < 4; ++mi){
            unsigned addr = ab + (uint32_t)((wm*64 + mi*16 + lrow)*80 + (k0 + lhi*8)*2);
            ldsm4(addr, afr[buf][mi][0], afr[buf][mi][1], afr[buf][mi][2], afr[buf][mi][3]);
        }
        #pragma unroll
        for (int nt = 0; nt < 4; ++nt){
            unsigned addr = bb + (uint32_t)((k0 + lrow)*272 + (wn*64 + nt*16 + lhi*8)*2);
            unsigned r0,r1,r2,r3;
            ldsm4t(addr, r0,r1,r2,r3);
            bfr[buf][nt*2  ][0]=r0; bfr[buf][nt*2  ][1]=r1;
            bfr[buf][nt*2+1][0]=r2; bfr[buf][nt*2+1][1]=r3;
        }
    };

    float acc[4][8][4] = {};

    #pragma unroll
    for (int s = 0; s < 3; s++){
        load_stage(s, s);
        asm volatile("cp.async.commit_group;");
    }
    asm volatile("cp.async.wait_group 2;");
    __syncthreads();
    ldfr(0, 0, 0);

    for (int c = 0; c < nchunks; ++c){
        int s = c & 3;
        ldfr(s, 1, 1);
        #pragma unroll
        for (int mi = 0; mi < 4; ++mi)
            #pragma unroll
            for (int ni = 0; ni < 8; ++ni)
                mma16816(acc[mi][ni], afr[0][mi], bfr[0][ni]);
        if (c + 3 < nchunks) load_stage((c+3)&3, c+3);
        asm volatile("cp.async.commit_group;");
        if (c + 1 < nchunks){
            asm volatile("cp.async.wait_group 2;");
            __syncthreads();
            ldfr((c+1)&3, 0, 0);
        }
        #pragma unroll
        for (int mi = 0; mi < 4; ++mi)
            #pragma unroll
            for (int ni = 0; ni < 8; ++ni)
                mma16816(acc[mi][ni], afr[1][mi], bfr[1][ni]);
    }

    // epilogue
    int g = lane >> 2, tig = lane & 3;
    #pragma unroll
    for (int mi = 0; mi < 4; ++mi){
        #pragma unroll
        for (int half = 0; half < 2; ++half){
            int row = m0 + wm*64 + mi*16 + g + half*8;
            if (row >= M) continue;
            float bqv = 0.f, mv0 = 0.f, mv1 = 0.f;
            if constexpr (EPI == 0){
                bqv = bq[row];
                mv0 = mask[row];
                mv1 = mask[N_ + row];
            }
            #pragma unroll
            for (int ni = 0; ni < 8; ++ni){
                int col = n0 + wn*64 + ni*8 + tig*2;
                int bb2 = col >= 384;
                int f = col - bb2*384;
                float v0 = acc[mi][ni][half*2+0];
                float v1 = acc[mi][ni][half*2+1];
                if constexpr (EPI == 0){
                    float mv = bb2 ? mv1 : mv0;
                    v0 += bqv*g_uvw[2*F_+f]   + mv*g_uvw[f]   + g_uvw[F_+f];
                    v1 += bqv*g_uvw[2*F_+f+1] + mv*g_uvw[f+1] + g_uvw[F_+f+1];
                    *(__half2*)&g_xp[((size_t)bb2*N_ + row)*F_ + f] = __floats2half2_rn(v0, v1);
                } else {
                    float* dst = &g_tmp[((size_t)bb2*S_ + row)*F_ + f];
                    atomicAdd(&dst[0], v0);
                    atomicAdd(&dst[1], v1);
                }
            }
        }
    }
}

// ---------------- attention scalars (fp16 xp reads) ----------------
__global__ void k_attn(const float* __restrict__ att_src, const float* __restrict__ att_dst){
    int gw = (blockIdx.x*blockDim.x + threadIdx.x) >> 5;
    if (gw >= BN_*H_) return;
    int lane = threadIdx.x & 31;
    int n = gw / H_, h = gw % H_;
    const __half* xrow = g_xp + (size_t)n*F_ + h*C_;
    __half2 h0 = ((const __half2*)xrow)[lane*2];
    __half2 h1 = ((const __half2*)xrow)[lane*2+1];
    float2 f0 = __half22float2(h0), f1 = __half22float2(h1);
    int c = lane*4;
    float s1 = f0.x*att_src[h*C_+c]   + f0.y*att_src[h*C_+c+1]
             + f1.x*att_src[h*C_+c+2] + f1.y*att_src[h*C_+c+3];
    float s2 = f0.x*att_dst[h*C_+c]   + f0.y*att_dst[h*C_+c+1]
             + f1.x*att_dst[h*C_+c+2] + f1.y*att_dst[h*C_+c+3];
    #pragma unroll
    for (int o = 16; o; o >>= 1){
        s1 += __shfl_xor_sync(0xffffffffu, s1, o);
        s2 += __shfl_xor_sync(0xffffffffu, s2, o);
    }
    if (lane == 0){ g_asrc[n*H_+h] = s1; g_adst[n*H_+h] = s2; }
}

// ---------------- CSR ----------------
__global__ void k_count(const int* __restrict__ ei){
    int e = blockIdx.x*blockDim.x + threadIdx.x;
    if (e >= BE_) return;
    int b = e / E_, j = e - b*E_;
    atomicAdd(&g_cnt[ei[E_ + j] + b*N_], 1);
}
__global__ void k_scan(){
    __shared__ int ssum[1024];
    int tid = threadIdx.x;
    const int CH = (BN_ + 1023)/1024;
    int base = tid*CH, s = 0;
    for (int i = 0; i < CH; i++){ int idx = base+i; if (idx < BN_) s += g_cnt[idx]; }
    ssum[tid] = s;
    __syncthreads();
    for (int off = 1; off < 1024; off <<= 1){
        int v = (tid >= off) ? ssum[tid-off] : 0;
        __syncthreads();
        ssum[tid] += v;
        __syncthreads();
    }
    int run = ssum[tid] - s;
    for (int i = 0; i < CH; i++){
        int idx = base+i;
        if (idx < BN_){ g_off[idx] = run; run += g_cnt[idx]; }
    }
    if (tid == 1023) g_off[BN_] = ssum[1023];
}
__global__ void k_scatter(const int* __restrict__ ei){
    int e = blockIdx.x*blockDim.x + threadIdx.x;
    if (e >= BE_) return;
    int b = e / E_, j = e - b*E_;
    int src = ei[j] + b*N_;
    int dst = ei[E_ + j] + b*N_;
    int pos = g_off[dst] + atomicAdd(&g_cur[dst], 1);
    g_esrc[pos] = src;
}

// ---------------- fused aggregation: one edge pass, inline softmax denom, x2 unroll ----
__global__ void k_aggregate(const float* __restrict__ bias_gat){
    int n = blockIdx.x;
    int tid = threadIdx.x;      // 0..95, covers cols [tid*4, tid*4+4)
    int h = tid >> 5;
    int beg = g_off[n], end = g_off[n+1];
    float ad = g_adst[n*3+h];
    const uint2* xp2 = (const uint2*)g_xp;    // 4 halves per uint2, 96 per row
    float4 acc = make_float4(0.f,0.f,0.f,0.f);
    float den = 0.f;
    int i = beg;
    for (; i + 2 <= end; i += 2){
        int s0 = g_esrc[i], s1 = g_esrc[i+1];
        float as0 = g_asrc[s0*3+h];
        float as1 = g_asrc[s1*3+h];
        uint2 r0 = xp2[(size_t)s0*96 + tid];
        uint2 r1 = xp2[(size_t)s1*96 + tid];
        float a0 = __expf(lrelu(as0 + ad));
        float a1 = __expf(lrelu(as1 + ad));
        float2 v00 = __half22float2(*(const __half2*)&r0.x);
        float2 v01 = __half22float2(*(const __half2*)&r0.y);
        float2 v10 = __half22float2(*(const __half2*)&r1.x);
        float2 v11 = __half22float2(*(const __half2*)&r1.y);
        acc.x = fmaf(v00.x, a0, acc.x); acc.y = fmaf(v00.y, a0, acc.y);
        acc.z = fmaf(v01.x, a0, acc.z); acc.w = fmaf(v01.y, a0, acc.w);
        acc.x = fmaf(v10.x, a1, acc.x); acc.y = fmaf(v10.y, a1, acc.y);
        acc.z = fmaf(v11.x, a1, acc.z); acc.w = fmaf(v11.y, a1, acc.w);
        den += a0 + a1;
    }
    if (i < end){
        int s0 = g_esrc[i];
        float a0 = __expf(lrelu(g_asrc[s0*3+h] + ad));
        uint2 r0 = xp2[(size_t)s0*96 + tid];
        float2 v00 = __half22float2(*(const __half2*)&r0.x);
        float2 v01 = __half22float2(*(const __half2*)&r0.y);
        acc.x = fmaf(v00.x, a0, acc.x); acc.y = fmaf(v00.y, a0, acc.y);
        acc.z = fmaf(v01.x, a0, acc.z); acc.w = fmaf(v01.y, a0, acc.w);
        den += a0;
    }
    // self-loop
    {
        float als = __expf(lrelu(g_asrc[n*3+h] + ad));
        uint2 raw = xp2[(size_t)n*96 + tid];
        float2 v0 = __half22float2(*(const __half2*)&raw.x);
        float2 v1 = __half22float2(*(const __half2*)&raw.y);
        acc.x = fmaf(v0.x, als, acc.x); acc.y = fmaf(v0.y, als, acc.y);
        acc.z = fmaf(v1.x, als, acc.z); acc.w = fmaf(v1.y, als, acc.w);
        den += als;
    }
    float rd = 1.f/den;
    float4 bg = ((const float4*)bias_gat)[tid];
    float o0 = fmaf(acc.x, rd, bg.x);
    float o1 = fmaf(acc.y, rd, bg.y);
    float o2 = fmaf(acc.z, rd, bg.z);
    float o3 = fmaf(acc.w, rd, bg.w);

    int b = n / N_;
    int k = n - b*N_;
    int col = b*384 + tid*4;
    union { __half bv[4]; uint2 u; } hh;
    hh.bv[0] = __float2half_rn(o0);
    hh.bv[1] = __float2half_rn(o1);
    hh.bv[2] = __float2half_rn(o2);
    hh.bv[3] = __float2half_rn(o3);
    *(uint2*)&g_gat2[(size_t)k*NW_ + col] = hh.u;
}

// ---------------- host ----------------
extern "C" void kernel_launch(void* const* d_in, const int* in_sizes, int n_in,
                              void* d_out, int out_size){
    const float* x_enc    = (const float*)d_in[0];
    const float* mask     = (const float*)d_in[1];
    const int*   ei       = (const int*)  d_in[2];
    const float* Wq       = (const float*)d_in[3];
    const float* bq       = (const float*)d_in[4];
    const float* Wm       = (const float*)d_in[5];
    const float* bm       = (const float*)d_in[6];
    const float* Wlin     = (const float*)d_in[7];
    const float* att_src  = (const float*)d_in[8];
    const float* att_dst  = (const float*)d_in[9];
    const float* bias_gat = (const float*)d_in[10];
    const float* Wproj    = (const float*)d_in[11];
    const float* bproj    = (const float*)d_in[12];
    const float* Wtemp    = (const float*)d_in[13];
    const float* btemp    = (const float*)d_in[14];
    float* out = (float*)d_out;

    void *pY2=0, *pWq2=0, *pWp2=0, *pG2=0, *pTmp=0;
    cudaGetSymbolAddress(&pY2,  g_Y2);
    cudaGetSymbolAddress(&pWq2, g_Wq2);
    cudaGetSymbolAddress(&pWp2, g_Wp2);
    cudaGetSymbolAddress(&pG2,  g_gat2);
    cudaGetSymbolAddress(&pTmp, g_tmp);

    cudaFuncSetAttribute(k_mma<0>, cudaFuncAttributeMaxDynamicSharedMemorySize, SMEM_MMA);
    cudaFuncSetAttribute(k_mma<1>, cudaFuncAttributeMaxDynamicSharedMemorySize, SMEM_MMA);

    k_uvw<<<3, 128>>>(Wlin, Wm, bm);
    k_gemm_bt<<<dim3(F_/64, S_/64, B_), 256>>>(
        x_enc, S_*D_, Wlin, nullptr, 0, D_, F_, nullptr, (__half*)pY2);
    k_split_wq2<<<(N_*(S_/4) + 255)/256, 256>>>(Wq);
    k_mma<0><<<dim3(NW_/128, (N_ + 127)/128, 1), 128, SMEM_MMA>>>(
        (const __half*)pWq2, 1024, N_, 1024,
        (const __half*)pY2, 512,
        KV_XP, NCH_XP, bq, mask);

    k_zero<<<(BN_ + 255)/256, 256>>>();
    k_count<<<(BE_ + 255)/256, 256>>>(ei);
    k_scan<<<1, 1024>>>();
    k_scatter<<<(BE_ + 255)/256, 256>>>(ei);

    k_attn<<<(BN_*H_*32 + 127)/128, 128>>>(att_src, att_dst);
    k_aggregate<<<BN_, 96>>>(bias_gat);

    k_split_wp2<<<(S_*(KPAD_/4) + 255)/256, 256>>>(Wproj);
    k_tmpinit<<<(B_*S_*F_ + 255)/256, 256>>>(bproj);
    k_mma<1><<<dim3(NW_/128, S_/128, NSPLIT_PJ), 128, SMEM_MMA>>>(
        (const __half*)pWp2, LDA_PJ, S_, LDA_PJ,
        (const __half*)pG2, KPAD_,
        KCHUNK_PJ, NCH_PJ, nullptr, nullptr);

    k_gemm_bt<<<dim3(DG_/64, (B_*S_)/64, 1), 256>>>(
        (const float*)pTmp, 0, Wtemp, out, 0, F_, DG_, btemp, nullptr);
}

// round 12
// speedup vs baseline: 1.2219x; 1.2206x over previous
#include <cuda_runtime.h>
#include <cuda_fp16.h>
#include <math.h>
#include <stdint.h>

#define B_  2
#define S_  512
#define N_  20000
#define D_  384
#define H_  3
#define C_  128
#define F_  384
#define E_  320000
#define DG_ 128
#define BN_ (B_*N_)
#define BE_ (B_*E_)

#define NW_      768
#define KV_XP    512                   // single fp16, no virtual-K
#define NCH_XP   16
#define KPAD_    20480
#define KV_PJ    KPAD_
#define NSPLIT_PJ 10
#define KCHUNK_PJ (KV_PJ/NSPLIT_PJ)    // 2048
#define NCH_PJ   (KCHUNK_PJ/32)        // 64
#define STG_A    10240                 // 128*40*2
#define STG_B    8704                  // 32*136*2
#define STG_SZ   (STG_A+STG_B)         // 18944
#define SMEM_MMA (4*STG_SZ)            // 75776

// ---------------- device scratch ----------------
__device__ __align__(16) __half g_Y2[512*NW_];                 // fp16 single
__device__ __align__(16) __half g_Wq2[(size_t)N_*512];         // fp16 single
__device__ __align__(16) __half g_Wp2[(size_t)S_*KPAD_];       // fp16 single, zero-padded
__device__ __align__(16) __half g_gat2[(size_t)KPAD_*NW_];     // fp16 single; pad rows stay 0
__device__ __align__(16) __half g_xp[(size_t)BN_*F_];          // fp16
__device__ float g_uvw[3*F_];
__device__ float g_asrc[BN_*H_];
__device__ float g_adst[BN_*H_];
__device__ int   g_off[BN_+1];
__device__ int   g_cnt[BN_];
__device__ int   g_cur[BN_];
__device__ int   g_esrc[BE_];
__device__ float g_tmp[B_*S_*F_];

__device__ __forceinline__ float lrelu(float x){ return x > 0.f ? x : 0.2f*x; }
__device__ __forceinline__ unsigned su(const void* p){
    return (unsigned)__cvta_generic_to_shared(p);
}
__device__ __forceinline__ void cpa16(unsigned dst, const void* src, bool pred){
    int sz = pred ? 16 : 0;
    asm volatile("cp.async.cg.shared.global [%0], [%1], 16, %2;\n"
                 :: "r"(dst), "l"(src), "r"(sz));
}
__device__ __forceinline__ void ldsm4(unsigned addr, unsigned &r0, unsigned &r1, unsigned &r2, unsigned &r3){
    asm volatile("ldmatrix.sync.aligned.m8n8.x4.shared.b16 {%0,%1,%2,%3}, [%4];\n"
                 : "=r"(r0),"=r"(r1),"=r"(r2),"=r"(r3) : "r"(addr));
}
__device__ __forceinline__ void ldsm4t(unsigned addr, unsigned &r0, unsigned &r1, unsigned &r2, unsigned &r3){
    asm volatile("ldmatrix.sync.aligned.m8n8.x4.trans.shared.b16 {%0,%1,%2,%3}, [%4];\n"
                 : "=r"(r0),"=r"(r1),"=r"(r2),"=r"(r3) : "r"(addr));
}
__device__ __forceinline__ void mma16816(float* c, const unsigned* a, const unsigned* b){
    asm volatile("mma.sync.aligned.m16n8k16.row.col.f32.f16.f16.f32 "
                 "{%0,%1,%2,%3},{%4,%5,%6,%7},{%8,%9},{%0,%1,%2,%3};\n"
                 : "+f"(c[0]),"+f"(c[1]),"+f"(c[2]),"+f"(c[3])
                 : "r"(a[0]),"r"(a[1]),"r"(a[2]),"r"(a[3]),"r"(b[0]),"r"(b[1]));
}

// ---------------- small kernels ----------------
__global__ void k_zero(){
    int i = blockIdx.x*blockDim.x + threadIdx.x;
    if (i < BN_){ g_cnt[i] = 0; g_cur[i] = 0; }
}
__global__ void k_uvw(const float* __restrict__ Wlin, const float* __restrict__ Wm,
                      const float* __restrict__ bm){
    int f = blockIdx.x*blockDim.x + threadIdx.x;
    if (f >= F_) return;
    float u=0.f, v=0.f, w=0.f;
    for (int d = 0; d < D_; d++){
        float wl = Wlin[f*D_ + d];
        u += wl*Wm[d]; v += wl*bm[d]; w += wl;
    }
    g_uvw[f]=u; g_uvw[F_+f]=v; g_uvw[2*F_+f]=w;
}
__global__ void k_tmpinit(const float* __restrict__ bproj){
    int i = blockIdx.x*blockDim.x + threadIdx.x;
    if (i >= B_*S_*F_) return;
    g_tmp[i] = bproj[(i / F_) % S_];
}

// ---------------- fp32 -> fp16 weight conversions (single, no split) ----------------
__global__ void k_cvt_wq(const float* __restrict__ Wq){
    int i4 = blockIdx.x*blockDim.x + threadIdx.x;
    if (i4 >= N_*(S_/4)) return;
    int m = i4 >> 7, k = (i4 & 127) << 2;
    float4 x = *(const float4*)(Wq + (size_t)m*S_ + k);
    union { __half b[4]; uint2 u; } hh;
    hh.b[0] = __float2half_rn(x.x);
    hh.b[1] = __float2half_rn(x.y);
    hh.b[2] = __float2half_rn(x.z);
    hh.b[3] = __float2half_rn(x.w);
    *(uint2*)&g_Wq2[(size_t)m*512 + k] = hh.u;
}
__global__ void k_cvt_wp(const float* __restrict__ Wproj){
    int i4 = blockIdx.x*blockDim.x + threadIdx.x;     // 512 * 5120
    if (i4 >= S_*(KPAD_/4)) return;
    int m = i4 / (KPAD_/4), k = (i4 % (KPAD_/4)) << 2;
    float4 x = (k < N_) ? *(const float4*)(Wproj + (size_t)m*N_ + k)
                        : make_float4(0.f,0.f,0.f,0.f);
    union { __half b[4]; uint2 u; } hh;
    hh.b[0] = __float2half_rn(x.x);
    hh.b[1] = __float2half_rn(x.y);
    hh.b[2] = __float2half_rn(x.z);
    hh.b[3] = __float2half_rn(x.w);
    *(uint2*)&g_Wp2[(size_t)m*KPAD_ + k] = hh.u;
}

// ---------------- fp32 tiled GEMM (small), C = A @ Bm^T ----------------
__global__ void k_gemm_bt(const float* __restrict__ A, int strideA,
                          const float* __restrict__ Bm,
                          float* __restrict__ C, int strideC,
                          int K, int Ncol, const float* __restrict__ bias_col,
                          __half* __restrict__ Ysplit){
    const float* Ab = A + blockIdx.z * strideA;
    int m0 = blockIdx.y*64, n0 = blockIdx.x*64;
    __shared__ float As[16][64];
    __shared__ float Bs[16][64];
    int tid = threadIdx.x;
    int tm = tid >> 4, tn = tid & 15;
    int lrow = tid >> 2, lcol = (tid & 3)*4;
    float acc[4][4] = {};
    for (int k0 = 0; k0 < K; k0 += 16){
        float4 av = *(const float4*)(Ab + (m0+lrow)*K + k0 + lcol);
        As[lcol+0][lrow]=av.x; As[lcol+1][lrow]=av.y; As[lcol+2][lrow]=av.z; As[lcol+3][lrow]=av.w;
        float4 bv = *(const float4*)(Bm + (n0+lrow)*K + k0 + lcol);
        Bs[lcol+0][lrow]=bv.x; Bs[lcol+1][lrow]=bv.y; Bs[lcol+2][lrow]=bv.z; Bs[lcol+3][lrow]=bv.w;
        __syncthreads();
        #pragma unroll
        for (int kk = 0; kk < 16; kk++){
            float4 a4 = *(const float4*)&As[kk][tm*4];
            float4 b4 = *(const float4*)&Bs[kk][tn*4];
            float ar[4]={a4.x,a4.y,a4.z,a4.w}, br[4]={b4.x,b4.y,b4.z,b4.w};
            #pragma unroll
            for (int i=0;i<4;i++)
                #pragma unroll
                for (int j=0;j<4;j++) acc[i][j]=fmaf(ar[i],br[j],acc[i][j]);
        }
        __syncthreads();
    }
    #pragma unroll
    for (int i=0;i<4;i++){
        int row = m0 + tm*4 + i;
        #pragma unroll
        for (int j=0;j<4;j++){
            int col = n0 + tn*4 + j;
            float v = acc[i][j];
            if (Ysplit){
                int gc = blockIdx.z*384 + col;
                Ysplit[(size_t)row*NW_ + gc] = __float2half_rn(v);
            } else {
                v += bias_col[col];
                (C + blockIdx.z*strideC)[row*Ncol + col] = v;
            }
        }
    }
}

// ---------------- fp16 mma.sync GEMM, 128x128 CTA, 64x64 warps, 4-stage, frag dbuf ----
template<int EPI>
__global__ __launch_bounds__(128, 2)
void k_mma(const __half* __restrict__ A, int lda, int M, int TA,
           const __half* __restrict__ Bm, int TB,
           int kchunk, int nchunks,
           const float* __restrict__ bq, const float* __restrict__ mask)
{
    extern __shared__ __align__(16) char smem[];
    uint32_t sbase = su(smem);

    const int tid = threadIdx.x, lane = tid & 31, wid = tid >> 5;
    const int wm = wid & 1, wn = wid >> 1;
    const int m0 = blockIdx.y*128, n0 = blockIdx.x*128;
    const int kbeg = blockIdx.z * kchunk;
    const int lrow = lane & 15, lhi = lane >> 4;

    auto load_stage = [&](int s, int c){
        int kv = kbeg + c*32;
        int ka = (kv >= TA) ? kv - TA : kv;
        int kb = (kv >= TB) ? kv - TB : kv;
        uint32_t ab = sbase + s*STG_SZ;
        uint32_t bb = ab + STG_A;
        #pragma unroll
        for (int i = tid; i < 512; i += 128){
            int row = i >> 2, seg = i & 3;
            int gr = m0 + row;
            const void* src = A + (size_t)(gr < M ? gr : M-1)*lda + ka + seg*8;
            cpa16(ab + (uint32_t)(row*80 + seg*16), src, gr < M);
        }
        #pragma unroll
        for (int i = tid; i < 512; i += 128){
            int row = i >> 4, seg = i & 15;
            const void* src = Bm + (size_t)(kb + row)*NW_ + n0 + seg*8;
            cpa16(bb + (uint32_t)(row*272 + seg*16), src, true);
        }
    };

    unsigned afr[2][4][4], bfr[2][8][2];
    auto ldfr = [&](int s, int kk, int buf){
        uint32_t ab = sbase + s*STG_SZ;
        uint32_t bb = ab + STG_A;
        int k0 = kk*16;
        #pragma unroll
        for (int mi = 0; mi < 4; ++mi){
            unsigned addr = ab + (uint32_t)((wm*64 + mi*16 + lrow)*80 + (k0 + lhi*8)*2);
            ldsm4(addr, afr[buf][mi][0], afr[buf][mi][1], afr[buf][mi][2], afr[buf][mi][3]);
        }
        #pragma unroll
        for (int nt = 0; nt < 4; ++nt){
            unsigned addr = bb + (uint32_t)((k0 + lrow)*272 + (wn*64 + nt*16 + lhi*8)*2);
            unsigned r0,r1,r2,r3;
            ldsm4t(addr, r0,r1,r2,r3);
            bfr[buf][nt*2  ][0]=r0; bfr[buf][nt*2  ][1]=r1;
            bfr[buf][nt*2+1][0]=r2; bfr[buf][nt*2+1][1]=r3;
        }
    };

    float acc[4][8][4] = {};

    #pragma unroll
    for (int s = 0; s < 3; s++){
        load_stage(s, s);
        asm volatile("cp.async.commit_group;");
    }
    asm volatile("cp.async.wait_group 2;");
    __syncthreads();
    ldfr(0, 0, 0);

    for (int c = 0; c < nchunks; ++c){
        int s = c & 3;
        ldfr(s, 1, 1);
        #pragma unroll
        for (int mi = 0; mi < 4; ++mi)
            #pragma unroll
            for (int ni = 0; ni < 8; ++ni)
                mma16816(acc[mi][ni], afr[0][mi], bfr[0][ni]);
        if (c + 3 < nchunks) load_stage((c+3)&3, c+3);
        asm volatile("cp.async.commit_group;");
        if (c + 1 < nchunks){
            asm volatile("cp.async.wait_group 2;");
            __syncthreads();
            ldfr((c+1)&3, 0, 0);
        }
        #pragma unroll
        for (int mi = 0; mi < 4; ++mi)
            #pragma unroll
            for (int ni = 0; ni < 8; ++ni)
                mma16816(acc[mi][ni], afr[1][mi], bfr[1][ni]);
    }

    // epilogue
    int g = lane >> 2, tig = lane & 3;
    #pragma unroll
    for (int mi = 0; mi < 4; ++mi){
        #pragma unroll
        for (int half = 0; half < 2; ++half){
            int row = m0 + wm*64 + mi*16 + g + half*8;
            if (row >= M) continue;
            float bqv = 0.f, mv0 = 0.f, mv1 = 0.f;
            if constexpr (EPI == 0){
                bqv = bq[row];
                mv0 = mask[row];
                mv1 = mask[N_ + row];
            }
            #pragma unroll
            for (int ni = 0; ni < 8; ++ni){
                int col = n0 + wn*64 + ni*8 + tig*2;
                int bb2 = col >= 384;
                int f = col - bb2*384;
                float v0 = acc[mi][ni][half*2+0];
                float v1 = acc[mi][ni][half*2+1];
                if constexpr (EPI == 0){
                    float mv = bb2 ? mv1 : mv0;
                    v0 += bqv*g_uvw[2*F_+f]   + mv*g_uvw[f]   + g_uvw[F_+f];
                    v1 += bqv*g_uvw[2*F_+f+1] + mv*g_uvw[f+1] + g_uvw[F_+f+1];
                    *(__half2*)&g_xp[((size_t)bb2*N_ + row)*F_ + f] = __floats2half2_rn(v0, v1);
                } else {
                    float* dst = &g_tmp[((size_t)bb2*S_ + row)*F_ + f];
                    atomicAdd(&dst[0], v0);
                    atomicAdd(&dst[1], v1);
                }
            }
        }
    }
}

// ---------------- attention scalars (fp16 xp reads) ----------------
__global__ void k_attn(const float* __restrict__ att_src, const float* __restrict__ att_dst){
    int gw = (blockIdx.x*blockDim.x + threadIdx.x) >> 5;
    if (gw >= BN_*H_) return;
    int lane = threadIdx.x & 31;
    int n = gw / H_, h = gw % H_;
    const __half* xrow = g_xp + (size_t)n*F_ + h*C_;
    __half2 h0 = ((const __half2*)xrow)[lane*2];
    __half2 h1 = ((const __half2*)xrow)[lane*2+1];
    float2 f0 = __half22float2(h0), f1 = __half22float2(h1);
    int c = lane*4;
    float s1 = f0.x*att_src[h*C_+c]   + f0.y*att_src[h*C_+c+1]
             + f1.x*att_src[h*C_+c+2] + f1.y*att_src[h*C_+c+3];
    float s2 = f0.x*att_dst[h*C_+c]   + f0.y*att_dst[h*C_+c+1]
             + f1.x*att_dst[h*C_+c+2] + f1.y*att_dst[h*C_+c+3];
    #pragma unroll
    for (int o = 16; o; o >>= 1){
        s1 += __shfl_xor_sync(0xffffffffu, s1, o);
        s2 += __shfl_xor_sync(0xffffffffu, s2, o);
    }
    if (lane == 0){ g_asrc[n*H_+h] = s1; g_adst[n*H_+h] = s2; }
}

// ---------------- CSR ----------------
__global__ void k_count(const int* __restrict__ ei){
    int e = blockIdx.x*blockDim.x + threadIdx.x;
    if (e >= BE_) return;
    int b = e / E_, j = e - b*E_;
    atomicAdd(&g_cnt[ei[E_ + j] + b*N_], 1);
}
__global__ void k_scan(){
    __shared__ int ssum[1024];
    int tid = threadIdx.x;
    const int CH = (BN_ + 1023)/1024;
    int base = tid*CH, s = 0;
    for (int i = 0; i < CH; i++){ int idx = base+i; if (idx < BN_) s += g_cnt[idx]; }
    ssum[tid] = s;
    __syncthreads();
    for (int off = 1; off < 1024; off <<= 1){
        int v = (tid >= off) ? ssum[tid-off] : 0;
        __syncthreads();
        ssum[tid] += v;
        __syncthreads();
    }
    int run = ssum[tid] - s;
    for (int i = 0; i < CH; i++){
        int idx = base+i;
        if (idx < BN_){ g_off[idx] = run; run += g_cnt[idx]; }
    }
    if (tid == 1023) g_off[BN_] = ssum[1023];
}
__global__ void k_scatter(const int* __restrict__ ei){
    int e = blockIdx.x*blockDim.x + threadIdx.x;
    if (e >= BE_) return;
    int b = e / E_, j = e - b*E_;
    int src = ei[j] + b*N_;
    int dst = ei[E_ + j] + b*N_;
    int pos = g_off[dst] + atomicAdd(&g_cur[dst], 1);
    g_esrc[pos] = src;
}

// ---------------- fused aggregation: one edge pass, inline softmax denom, x2 unroll ----
__global__ void k_aggregate(const float* __restrict__ bias_gat){
    int n = blockIdx.x;
    int tid = threadIdx.x;      // 0..95, covers cols [tid*4, tid*4+4)
    int h = tid >> 5;
    int beg = g_off[n], end = g_off[n+1];
    float ad = g_adst[n*3+h];
    const uint2* xp2 = (const uint2*)g_xp;    // 4 halves per uint2, 96 per row
    float4 acc = make_float4(0.f,0.f,0.f,0.f);
    float den = 0.f;
    int i = beg;
    for (; i + 2 <= end; i += 2){
        int s0 = g_esrc[i], s1 = g_esrc[i+1];
        float as0 = g_asrc[s0*3+h];
        float as1 = g_asrc[s1*3+h];
        uint2 r0 = xp2[(size_t)s0*96 + tid];
        uint2 r1 = xp2[(size_t)s1*96 + tid];
        float a0 = __expf(lrelu(as0 + ad));
        float a1 = __expf(lrelu(as1 + ad));
        float2 v00 = __half22float2(*(const __half2*)&r0.x);
        float2 v01 = __half22float2(*(const __half2*)&r0.y);
        float2 v10 = __half22float2(*(const __half2*)&r1.x);
        float2 v11 = __half22float2(*(const __half2*)&r1.y);
        acc.x = fmaf(v00.x, a0, acc.x); acc.y = fmaf(v00.y, a0, acc.y);
        acc.z = fmaf(v01.x, a0, acc.z); acc.w = fmaf(v01.y, a0, acc.w);
        acc.x = fmaf(v10.x, a1, acc.x); acc.y = fmaf(v10.y, a1, acc.y);
        acc.z = fmaf(v11.x, a1, acc.z); acc.w = fmaf(v11.y, a1, acc.w);
        den += a0 + a1;
    }
    if (i < end){
        int s0 = g_esrc[i];
        float a0 = __expf(lrelu(g_asrc[s0*3+h] + ad));
        uint2 r0 = xp2[(size_t)s0*96 + tid];
        float2 v00 = __half22float2(*(const __half2*)&r0.x);
        float2 v01 = __half22float2(*(const __half2*)&r0.y);
        acc.x = fmaf(v00.x, a0, acc.x); acc.y = fmaf(v00.y, a0, acc.y);
        acc.z = fmaf(v01.x, a0, acc.z); acc.w = fmaf(v01.y, a0, acc.w);
        den += a0;
    }
    // self-loop
    {
        float als = __expf(lrelu(g_asrc[n*3+h] + ad));
        uint2 raw = xp2[(size_t)n*96 + tid];
        float2 v0 = __half22float2(*(const __half2*)&raw.x);
        float2 v1 = __half22float2(*(const __half2*)&raw.y);
        acc.x = fmaf(v0.x, als, acc.x); acc.y = fmaf(v0.y, als, acc.y);
        acc.z = fmaf(v1.x, als, acc.z); acc.w = fmaf(v1.y, als, acc.w);
        den += als;
    }
    float rd = 1.f/den;
    float4 bg = ((const float4*)bias_gat)[tid];
    float o0 = fmaf(acc.x, rd, bg.x);
    float o1 = fmaf(acc.y, rd, bg.y);
    float o2 = fmaf(acc.z, rd, bg.z);
    float o3 = fmaf(acc.w, rd, bg.w);

    int b = n / N_;
    int k = n - b*N_;
    int col = b*384 + tid*4;
    union { __half bv[4]; uint2 u; } hh;
    hh.bv[0] = __float2half_rn(o0);
    hh.bv[1] = __float2half_rn(o1);
    hh.bv[2] = __float2half_rn(o2);
    hh.bv[3] = __float2half_rn(o3);
    *(uint2*)&g_gat2[(size_t)k*NW_ + col] = hh.u;
}

// ---------------- host ----------------
extern "C" void kernel_launch(void* const* d_in, const int* in_sizes, int n_in,
                              void* d_out, int out_size){
    const float* x_enc    = (const float*)d_in[0];
    const float* mask     = (const float*)d_in[1];
    const int*   ei       = (const int*)  d_in[2];
    const float* Wq       = (const float*)d_in[3];
    const float* bq       = (const float*)d_in[4];
    const float* Wm       = (const float*)d_in[5];
    const float* bm       = (const float*)d_in[6];
    const float* Wlin     = (const float*)d_in[7];
    const float* att_src  = (const float*)d_in[8];
    const float* att_dst  = (const float*)d_in[9];
    const float* bias_gat = (const float*)d_in[10];
    const float* Wproj    = (const float*)d_in[11];
    const float* bproj    = (const float*)d_in[12];
    const float* Wtemp    = (const float*)d_in[13];
    const float* btemp    = (const float*)d_in[14];
    float* out = (float*)d_out;

    void *pY2=0, *pWq2=0, *pWp2=0, *pG2=0, *pTmp=0;
    cudaGetSymbolAddress(&pY2,  g_Y2);
    cudaGetSymbolAddress(&pWq2, g_Wq2);
    cudaGetSymbolAddress(&pWp2, g_Wp2);
    cudaGetSymbolAddress(&pG2,  g_gat2);
    cudaGetSymbolAddress(&pTmp, g_tmp);

    cudaFuncSetAttribute(k_mma<0>, cudaFuncAttributeMaxDynamicSharedMemorySize, SMEM_MMA);
    cudaFuncSetAttribute(k_mma<1>, cudaFuncAttributeMaxDynamicSharedMemorySize, SMEM_MMA);

    k_uvw<<<3, 128>>>(Wlin, Wm, bm);
    k_gemm_bt<<<dim3(F_/64, S_/64, B_), 256>>>(
        x_enc, S_*D_, Wlin, nullptr, 0, D_, F_, nullptr, (__half*)pY2);
    k_cvt_wq<<<(N_*(S_/4) + 255)/256, 256>>>(Wq);
    // xp = Wq @ Y (+affine): single fp16, K=512
    k_mma<0><<<dim3(NW_/128, (N_ + 127)/128, 1), 128, SMEM_MMA>>>(
        (const __half*)pWq2, 512, N_, 512,
        (const __half*)pY2, 512,
        KV_XP, NCH_XP, bq, mask);

    k_zero<<<(BN_ + 255)/256, 256>>>();
    k_count<<<(BE_ + 255)/256, 256>>>(ei);
    k_scan<<<1, 1024>>>();
    k_scatter<<<(BE_ + 255)/256, 256>>>(ei);

    k_attn<<<(BN_*H_*32 + 127)/128, 128>>>(att_src, att_dst);
    k_aggregate<<<BN_, 96>>>(bias_gat);

    k_cvt_wp<<<(S_*(KPAD_/4) + 255)/256, 256>>>(Wproj);
    k_tmpinit<<<(B_*S_*F_ + 255)/256, 256>>>(bproj);
    // proj: single fp16, K=20480, 10 splits (240 CTAs = one wave)
    k_mma<1><<<dim3(NW_/128, S_/128, NSPLIT_PJ), 128, SMEM_MMA>>>(
        (const __half*)pWp2, KPAD_, S_, KPAD_,
        (const __half*)pG2, KPAD_,
        KCHUNK_PJ, NCH_PJ, nullptr, nullptr);

    k_gemm_bt<<<dim3(DG_/64, (B_*S_)/64, 1), 256>>>(
        (const float*)pTmp, 0, Wtemp, out, 0, F_, DG_, btemp, nullptr);
}

// round 13
// speedup vs baseline: 1.2399x; 1.0148x over previous
#include <cuda_runtime.h>
#include <cuda_fp16.h>
#include <math.h>
#include <stdint.h>

#define B_  2
#define S_  512
#define N_  20000
#define D_  384
#define H_  3
#define C_  128
#define F_  384
#define E_  320000
#define DG_ 128
#define BN_ (B_*N_)
#define BE_ (B_*E_)

#define NW_      768
#define KPAD_    20480
#define TOTCH_PJ 640                   // 20480/32
#define NSPLIT_PJ 12                   // uneven ranges, 288 CTAs = one wave
#define STG_A    10240                 // 128*40*2
#define STG_B    8704                  // 32*136*2
#define STG_SZ   (STG_A+STG_B)         // 18944
#define SMEM_MMA (4*STG_SZ)            // 75776

// ---------------- device scratch ----------------
__device__ __align__(16) __half g_Y2[512*NW_];                 // fp16 single
__device__ __align__(16) __half g_Wq2[(size_t)N_*512];         // fp16 single
__device__ __align__(16) __half g_Wp2[(size_t)S_*KPAD_];       // fp16 single, zero-padded
__device__ __align__(16) __half g_gat2[(size_t)KPAD_*NW_];     // fp16 single; pad rows stay 0
__device__ __align__(16) __half g_xp[(size_t)BN_*F_];          // fp16
__device__ float g_uvw[3*F_];
__device__ float g_asrc[BN_*H_];
__device__ float g_adst[BN_*H_];
__device__ int   g_off[BN_+1];
__device__ int   g_cnt[BN_];
__device__ int   g_cur[BN_];
__device__ int   g_esrc[BE_];
__device__ float g_tmp[B_*S_*F_];

__device__ __forceinline__ float lrelu(float x){ return x > 0.f ? x : 0.2f*x; }
__device__ __forceinline__ unsigned su(const void* p){
    return (unsigned)__cvta_generic_to_shared(p);
}
__device__ __forceinline__ void cpa16(unsigned dst, const void* src, bool pred){
    int sz = pred ? 16 : 0;
    asm volatile("cp.async.cg.shared.global [%0], [%1], 16, %2;\n"
                 :: "r"(dst), "l"(src), "r"(sz));
}
__device__ __forceinline__ void ldsm4(unsigned addr, unsigned &r0, unsigned &r1, unsigned &r2, unsigned &r3){
    asm volatile("ldmatrix.sync.aligned.m8n8.x4.shared.b16 {%0,%1,%2,%3}, [%4];\n"
                 : "=r"(r0),"=r"(r1),"=r"(r2),"=r"(r3) : "r"(addr));
}
__device__ __forceinline__ void ldsm4t(unsigned addr, unsigned &r0, unsigned &r1, unsigned &r2, unsigned &r3){
    asm volatile("ldmatrix.sync.aligned.m8n8.x4.trans.shared.b16 {%0,%1,%2,%3}, [%4];\n"
                 : "=r"(r0),"=r"(r1),"=r"(r2),"=r"(r3) : "r"(addr));
}
__device__ __forceinline__ void mma16816(float* c, const unsigned* a, const unsigned* b){
    asm volatile("mma.sync.aligned.m16n8k16.row.col.f32.f16.f16.f32 "
                 "{%0,%1,%2,%3},{%4,%5,%6,%7},{%8,%9},{%0,%1,%2,%3};\n"
                 : "+f"(c[0]),"+f"(c[1]),"+f"(c[2]),"+f"(c[3])
                 : "r"(a[0]),"r"(a[1]),"r"(a[2]),"r"(a[3]),"r"(b[0]),"r"(b[1]));
}

// ---------------- merged setup: cnt/cur, asrc/adst zero, tmp init, uvw ----------------
__global__ void k_setup(const float* __restrict__ Wlin, const float* __restrict__ Wm,
                        const float* __restrict__ bm, const float* __restrict__ bproj){
    int i = blockIdx.x*blockDim.x + threadIdx.x;
    if (i < F_){
        float u=0.f, v=0.f, w=0.f;
        for (int d = 0; d < D_; d++){
            float wl = Wlin[i*D_ + d];
            u += wl*Wm[d]; v += wl*bm[d]; w += wl;
        }
        g_uvw[i]=u; g_uvw[F_+i]=v; g_uvw[2*F_+i]=w;
    }
    if (i < BN_){ g_cnt[i] = 0; g_cur[i] = 0; }
    if (i < BN_*H_){ g_asrc[i] = 0.f; g_adst[i] = 0.f; }
    if (i < B_*S_*F_) g_tmp[i] = bproj[(i / F_) % S_];
}

// ---------------- fp32 -> fp16 weight conversions ----------------
__global__ void k_cvt_wq(const float* __restrict__ Wq){
    int i4 = blockIdx.x*blockDim.x + threadIdx.x;
    if (i4 >= N_*(S_/4)) return;
    int m = i4 >> 7, k = (i4 & 127) << 2;
    float4 x = *(const float4*)(Wq + (size_t)m*S_ + k);
    union { __half b[4]; uint2 u; } hh;
    hh.b[0] = __float2half_rn(x.x);
    hh.b[1] = __float2half_rn(x.y);
    hh.b[2] = __float2half_rn(x.z);
    hh.b[3] = __float2half_rn(x.w);
    *(uint2*)&g_Wq2[(size_t)m*512 + k] = hh.u;
}
__global__ void k_cvt_wp(const float* __restrict__ Wproj){
    int i4 = blockIdx.x*blockDim.x + threadIdx.x;     // 512 * 5120
    if (i4 >= S_*(KPAD_/4)) return;
    int m = i4 / (KPAD_/4), k = (i4 % (KPAD_/4)) << 2;
    float4 x = (k < N_) ? *(const float4*)(Wproj + (size_t)m*N_ + k)
                        : make_float4(0.f,0.f,0.f,0.f);
    union { __half b[4]; uint2 u; } hh;
    hh.b[0] = __float2half_rn(x.x);
    hh.b[1] = __float2half_rn(x.y);
    hh.b[2] = __float2half_rn(x.z);
    hh.b[3] = __float2half_rn(x.w);
    *(uint2*)&g_Wp2[(size_t)m*KPAD_ + k] = hh.u;
}

// ---------------- fp32 tiled GEMM (small), C = A @ Bm^T ----------------
__global__ void k_gemm_bt(const float* __restrict__ A, int strideA,
                          const float* __restrict__ Bm,
                          float* __restrict__ C, int strideC,
                          int K, int Ncol, const float* __restrict__ bias_col,
                          __half* __restrict__ Ysplit){
    const float* Ab = A + blockIdx.z * strideA;
    int m0 = blockIdx.y*64, n0 = blockIdx.x*64;
    __shared__ float As[16][64];
    __shared__ float Bs[16][64];
    int tid = threadIdx.x;
    int tm = tid >> 4, tn = tid & 15;
    int lrow = tid >> 2, lcol = (tid & 3)*4;
    float acc[4][4] = {};
    for (int k0 = 0; k0 < K; k0 += 16){
        float4 av = *(const float4*)(Ab + (m0+lrow)*K + k0 + lcol);
        As[lcol+0][lrow]=av.x; As[lcol+1][lrow]=av.y; As[lcol+2][lrow]=av.z; As[lcol+3][lrow]=av.w;
        float4 bv = *(const float4*)(Bm + (n0+lrow)*K + k0 + lcol);
        Bs[lcol+0][lrow]=bv.x; Bs[lcol+1][lrow]=bv.y; Bs[lcol+2][lrow]=bv.z; Bs[lcol+3][lrow]=bv.w;
        __syncthreads();
        #pragma unroll
        for (int kk = 0; kk < 16; kk++){
            float4 a4 = *(const float4*)&As[kk][tm*4];
            float4 b4 = *(const float4*)&Bs[kk][tn*4];
            float ar[4]={a4.x,a4.y,a4.z,a4.w}, br[4]={b4.x,b4.y,b4.z,b4.w};
            #pragma unroll
            for (int i=0;i<4;i++)
                #pragma unroll
                for (int j=0;j<4;j++) acc[i][j]=fmaf(ar[i],br[j],acc[i][j]);
        }
        __syncthreads();
    }
    #pragma unroll
    for (int i=0;i<4;i++){
        int row = m0 + tm*4 + i;
        #pragma unroll
        for (int j=0;j<4;j++){
            int col = n0 + tn*4 + j;
            float v = acc[i][j];
            if (Ysplit){
                int gc = blockIdx.z*384 + col;
                Ysplit[(size_t)row*NW_ + gc] = __float2half_rn(v);
            } else {
                v += bias_col[col];
                (C + blockIdx.z*strideC)[row*Ncol + col] = v;
            }
        }
    }
}

// ---------------- fp16 mma.sync GEMM, 128x128 CTA, 64x64 warps, 4-stage, frag dbuf ----
// EPI=0: xp epilogue (fused affine + fused attention partial dots via atomics)
// EPI=1: proj epilogue (atomicAdd -> g_tmp); uneven K-splits via totch/nsplit
template<int EPI>
__global__ __launch_bounds__(128, 2)
void k_mma(const __half* __restrict__ A, int lda, int M,
           const __half* __restrict__ Bm,
           int totch, int nsplit,
           const float* __restrict__ bq, const float* __restrict__ mask,
           const float* __restrict__ att_src, const float* __restrict__ att_dst)
{
    extern __shared__ __align__(16) char smem[];
    uint32_t sbase = su(smem);

    const int tid = threadIdx.x, lane = tid & 31, wid = tid >> 5;
    const int wm = wid & 1, wn = wid >> 1;
    const int m0 = blockIdx.y*128, n0 = blockIdx.x*128;
    const int cbeg = (blockIdx.z * totch) / nsplit;
    const int cend = ((blockIdx.z + 1) * totch) / nsplit;
    const int nchunks = cend - cbeg;
    const int kbeg = cbeg * 32;
    const int lrow = lane & 15, lhi = lane >> 4;

    auto load_stage = [&](int s, int c){
        int kv = kbeg + c*32;
        uint32_t ab = sbase + s*STG_SZ;
        uint32_t bb = ab + STG_A;
        #pragma unroll
        for (int i = tid; i < 512; i += 128){
            int row = i >> 2, seg = i & 3;
            int gr = m0 + row;
            const void* src = A + (size_t)(gr < M ? gr : M-1)*lda + kv + seg*8;
            cpa16(ab + (uint32_t)(row*80 + seg*16), src, gr < M);
        }
        #pragma unroll
        for (int i = tid; i < 512; i += 128){
            int row = i >> 4, seg = i & 15;
            const void* src = Bm + (size_t)(kv + row)*NW_ + n0 + seg*8;
            cpa16(bb + (uint32_t)(row*272 + seg*16), src, true);
        }
    };

    unsigned afr[2][4][4], bfr[2][8][2];
    auto ldfr = [&](int s, int kk, int buf){
        uint32_t ab = sbase + s*STG_SZ;
        uint32_t bb = ab + STG_A;
        int k0 = kk*16;
        #pragma unroll
        for (int mi = 0; mi < 4; ++mi){
            unsigned addr = ab + (uint32_t)((wm*64 + mi*16 + lrow)*80 + (k0 + lhi*8)*2);
            ldsm4(addr, afr[buf][mi][0], afr[buf][mi][1], afr[buf][mi][2], afr[buf][mi][3]);
        }
        #pragma unroll
        for (int nt = 0; nt < 4; ++nt){
            unsigned addr = bb + (uint32_t)((k0 + lrow)*272 + (wn*64 + nt*16 + lhi*8)*2);
            unsigned r0,r1,r2,r3;
            ldsm4t(addr, r0,r1,r2,r3);
            bfr[buf][nt*2  ][0]=r0; bfr[buf][nt*2  ][1]=r1;
            bfr[buf][nt*2+1][0]=r2; bfr[buf][nt*2+1][1]=r3;
        }
    };

    float acc[4][8][4] = {};

    #pragma unroll
    for (int s = 0; s < 3; s++){
        load_stage(s, s);
        asm volatile("cp.async.commit_group;");
    }
    asm volatile("cp.async.wait_group 2;");
    __syncthreads();
    ldfr(0, 0, 0);

    for (int c = 0; c < nchunks; ++c){
        int s = c & 3;
        ldfr(s, 1, 1);
        #pragma unroll
        for (int mi = 0; mi < 4; ++mi)
            #pragma unroll
            for (int ni = 0; ni < 8; ++ni)
                mma16816(acc[mi][ni], afr[0][mi], bfr[0][ni]);
        if (c + 3 < nchunks) load_stage((c+3)&3, c+3);
        asm volatile("cp.async.commit_group;");
        if (c + 1 < nchunks){
            asm volatile("cp.async.wait_group 2;");
            __syncthreads();
            ldfr((c+1)&3, 0, 0);
        }
        #pragma unroll
        for (int mi = 0; mi < 4; ++mi)
            #pragma unroll
            for (int ni = 0; ni < 8; ++ni)
                mma16816(acc[mi][ni], afr[1][mi], bfr[1][ni]);
    }

    // epilogue
    int g = lane >> 2, tig = lane & 3;
    const int bb2 = n0 >= 384;             // whole 128-col block is one (batch, head)
    const int hb  = (n0 - bb2*384) >> 7;
    #pragma unroll
    for (int mi = 0; mi < 4; ++mi){
        #pragma unroll
        for (int half = 0; half < 2; ++half){
            int row = m0 + wm*64 + mi*16 + g + half*8;
            if (row >= M) continue;
            if constexpr (EPI == 0){
                float bqv = bq[row];
                float mv  = mask[bb2*N_ + row];
                float s1 = 0.f, s2 = 0.f;
                #pragma unroll
                for (int ni = 0; ni < 8; ++ni){
                    int c = wn*64 + ni*8 + tig*2;
                    int f = hb*128 + c;
                    float v0 = acc[mi][ni][half*2+0]
                             + bqv*g_uvw[2*F_+f]   + mv*g_uvw[f]   + g_uvw[F_+f];
                    float v1 = acc[mi][ni][half*2+1]
                             + bqv*g_uvw[2*F_+f+1] + mv*g_uvw[f+1] + g_uvw[F_+f+1];
                    *(__half2*)&g_xp[((size_t)bb2*N_ + row)*F_ + f] = __floats2half2_rn(v0, v1);
                    s1 = fmaf(v0, att_src[hb*C_+c], fmaf(v1, att_src[hb*C_+c+1], s1));
                    s2 = fmaf(v0, att_dst[hb*C_+c], fmaf(v1, att_dst[hb*C_+c+1], s2));
                }
                s1 += __shfl_xor_sync(0xffffffffu, s1, 1);
                s1 += __shfl_xor_sync(0xffffffffu, s1, 2);
                s2 += __shfl_xor_sync(0xffffffffu, s2, 1);
                s2 += __shfl_xor_sync(0xffffffffu, s2, 2);
                if (tig == 0){
                    atomicAdd(&g_asrc[((size_t)bb2*N_ + row)*3 + hb], s1);
                    atomicAdd(&g_adst[((size_t)bb2*N_ + row)*3 + hb], s2);
                }
            } else {
                #pragma unroll
                for (int ni = 0; ni < 8; ++ni){
                    int c = wn*64 + ni*8 + tig*2;
                    int f = hb*128 + c;
                    float* dst = &g_tmp[((size_t)bb2*S_ + row)*F_ + f];
                    atomicAdd(&dst[0], acc[mi][ni][half*2+0]);
                    atomicAdd(&dst[1], acc[mi][ni][half*2+1]);
                }
            }
        }
    }
}

// ---------------- CSR ----------------
__global__ void k_count(const int* __restrict__ ei){
    int e = blockIdx.x*blockDim.x + threadIdx.x;
    if (e >= BE_) return;
    int b = e / E_, j = e - b*E_;
    atomicAdd(&g_cnt[ei[E_ + j] + b*N_], 1);
}
__global__ void k_scan(){
    __shared__ int ssum[1024];
    int tid = threadIdx.x;
    const int CH = (BN_ + 1023)/1024;
    int base = tid*CH, s = 0;
    for (int i = 0; i < CH; i++){ int idx = base+i; if (idx < BN_) s += g_cnt[idx]; }
    ssum[tid] = s;
    __syncthreads();
    for (int off = 1; off < 1024; off <<= 1){
        int v = (tid >= off) ? ssum[tid-off] : 0;
        __syncthreads();
        ssum[tid] += v;
        __syncthreads();
    }
    int run = ssum[tid] - s;
    for (int i = 0; i < CH; i++){
        int idx = base+i;
        if (idx < BN_){ g_off[idx] = run; run += g_cnt[idx]; }
    }
    if (tid == 1023) g_off[BN_] = ssum[1023];
}
__global__ void k_scatter(const int* __restrict__ ei){
    int e = blockIdx.x*blockDim.x + threadIdx.x;
    if (e >= BE_) return;
    int b = e / E_, j = e - b*E_;
    int src = ei[j] + b*N_;
    int dst = ei[E_ + j] + b*N_;
    int pos = g_off[dst] + atomicAdd(&g_cur[dst], 1);
    g_esrc[pos] = src;
}

// ---------------- fused aggregation: one edge pass, inline softmax denom, x2 unroll ----
__global__ void k_aggregate(const float* __restrict__ bias_gat){
    int n = blockIdx.x;
    int tid = threadIdx.x;      // 0..95, covers cols [tid*4, tid*4+4)
    int h = tid >> 5;
    int beg = g_off[n], end = g_off[n+1];
    float ad = g_adst[n*3+h];
    const uint2* xp2 = (const uint2*)g_xp;    // 4 halves per uint2, 96 per row
    float4 acc = make_float4(0.f,0.f,0.f,0.f);
    float den = 0.f;
    int i = beg;
    for (; i + 2 <= end; i += 2){
        int s0 = g_esrc[i], s1 = g_esrc[i+1];
        float as0 = g_asrc[s0*3+h];
        float as1 = g_asrc[s1*3+h];
        uint2 r0 = xp2[(size_t)s0*96 + tid];
        uint2 r1 = xp2[(size_t)s1*96 + tid];
        float a0 = __expf(lrelu(as0 + ad));
        float a1 = __expf(lrelu(as1 + ad));
        float2 v00 = __half22float2(*(const __half2*)&r0.x);
        float2 v01 = __half22float2(*(const __half2*)&r0.y);
        float2 v10 = __half22float2(*(const __half2*)&r1.x);
        float2 v11 = __half22float2(*(const __half2*)&r1.y);
        acc.x = fmaf(v00.x, a0, acc.x); acc.y = fmaf(v00.y, a0, acc.y);
        acc.z = fmaf(v01.x, a0, acc.z); acc.w = fmaf(v01.y, a0, acc.w);
        acc.x = fmaf(v10.x, a1, acc.x); acc.y = fmaf(v10.y, a1, acc.y);
        acc.z = fmaf(v11.x, a1, acc.z); acc.w = fmaf(v11.y, a1, acc.w);
        den += a0 + a1;
    }
    if (i < end){
        int s0 = g_esrc[i];
        float a0 = __expf(lrelu(g_asrc[s0*3+h] + ad));
        uint2 r0 = xp2[(size_t)s0*96 + tid];
        float2 v00 = __half22float2(*(const __half2*)&r0.x);
        float2 v01 = __half22float2(*(const __half2*)&r0.y);
        acc.x = fmaf(v00.x, a0, acc.x); acc.y = fmaf(v00.y, a0, acc.y);
        acc.z = fmaf(v01.x, a0, acc.z); acc.w = fmaf(v01.y, a0, acc.w);
        den += a0;
    }
    // self-loop
    {
        float als = __expf(lrelu(g_asrc[n*3+h] + ad));
        uint2 raw = xp2[(size_t)n*96 + tid];
        float2 v0 = __half22float2(*(const __half2*)&raw.x);
        float2 v1 = __half22float2(*(const __half2*)&raw.y);
        acc.x = fmaf(v0.x, als, acc.x); acc.y = fmaf(v0.y, als, acc.y);
        acc.z = fmaf(v1.x, als, acc.z); acc.w = fmaf(v1.y, als, acc.w);
        den += als;
    }
    float rd = 1.f/den;
    float4 bg = ((const float4*)bias_gat)[tid];
    float o0 = fmaf(acc.x, rd, bg.x);
    float o1 = fmaf(acc.y, rd, bg.y);
    float o2 = fmaf(acc.z, rd, bg.z);
    float o3 = fmaf(acc.w, rd, bg.w);

    int b = n / N_;
    int k = n - b*N_;
    int col = b*384 + tid*4;
    union { __half bv[4]; uint2 u; } hh;
    hh.bv[0] = __float2half_rn(o0);
    hh.bv[1] = __float2half_rn(o1);
    hh.bv[2] = __float2half_rn(o2);
    hh.bv[3] = __float2half_rn(o3);
    *(uint2*)&g_gat2[(size_t)k*NW_ + col] = hh.u;
}

// ---------------- host ----------------
extern "C" void kernel_launch(void* const* d_in, const int* in_sizes, int n_in,
                              void* d_out, int out_size){
    const float* x_enc    = (const float*)d_in[0];
    const float* mask     = (const float*)d_in[1];
    const int*   ei       = (const int*)  d_in[2];
    const float* Wq       = (const float*)d_in[3];
    const float* bq       = (const float*)d_in[4];
    const float* Wm       = (const float*)d_in[5];
    const float* bm       = (const float*)d_in[6];
    const float* Wlin     = (const float*)d_in[7];
    const float* att_src  = (const float*)d_in[8];
    const float* att_dst  = (const float*)d_in[9];
    const float* bias_gat = (const float*)d_in[10];
    const float* Wproj    = (const float*)d_in[11];
    const float* bproj    = (const float*)d_in[12];
    const float* Wtemp    = (const float*)d_in[13];
    const float* btemp    = (const float*)d_in[14];
    float* out = (float*)d_out;

    void *pY2=0, *pWq2=0, *pWp2=0, *pG2=0, *pTmp=0;
    cudaGetSymbolAddress(&pY2,  g_Y2);
    cudaGetSymbolAddress(&pWq2, g_Wq2);
    cudaGetSymbolAddress(&pWp2, g_Wp2);
    cudaGetSymbolAddress(&pG2,  g_gat2);
    cudaGetSymbolAddress(&pTmp, g_tmp);

    cudaFuncSetAttribute(k_mma<0>, cudaFuncAttributeMaxDynamicSharedMemorySize, SMEM_MMA);
    cudaFuncSetAttribute(k_mma<1>, cudaFuncAttributeMaxDynamicSharedMemorySize, SMEM_MMA);

    // 1) merged setup (uvw, cnt/cur, asrc/adst zero, tmp init)
    k_setup<<<(B_*S_*F_ + 255)/256, 256>>>(Wlin, Wm, bm, bproj);
    // 2) Y = x_enc @ Wlin^T -> fp16
    k_gemm_bt<<<dim3(F_/64, S_/64, B_), 256>>>(
        x_enc, S_*D_, Wlin, nullptr, 0, D_, F_, nullptr, (__half*)pY2);
    // 3) Wq -> fp16
    k_cvt_wq<<<(N_*(S_/4) + 255)/256, 256>>>(Wq);
    // 4) xp GEMM + fused affine + fused attention dots
    k_mma<0><<<dim3(NW_/128, (N_ + 127)/128, 1), 128, SMEM_MMA>>>(
        (const __half*)pWq2, 512, N_,
        (const __half*)pY2,
        16, 1, bq, mask, att_src, att_dst);

    // CSR build
    k_count<<<(BE_ + 255)/256, 256>>>(ei);
    k_scan<<<1, 1024>>>();
    k_scatter<<<(BE_ + 255)/256, 256>>>(ei);

    // aggregation (fused softmax)
    k_aggregate<<<BN_, 96>>>(bias_gat);

    // proj
    k_cvt_wp<<<(S_*(KPAD_/4) + 255)/256, 256>>>(Wproj);
    k_mma<1><<<dim3(NW_/128, S_/128, NSPLIT_PJ), 128, SMEM_MMA>>>(
        (const __half*)pWp2, KPAD_, S_,
        (const __half*)pG2,
        TOTCH_PJ, NSPLIT_PJ, nullptr, nullptr, nullptr, nullptr);

    // final out
    k_gemm_bt<<<dim3(DG_/64, (B_*S_)/64, 1), 256>>>(
        (const float*)pTmp, 0, Wtemp, out, 0, F_, DG_, btemp, nullptr);
}

// round 14
// speedup vs baseline: 1.2959x; 1.0452x over previous
#include <cuda_runtime.h>
#include <cuda_fp16.h>
#include <math.h>
#include <stdint.h>

#define B_  2
#define S_  512
#define N_  20000
#define D_  384
#define H_  3
#define C_  128
#define F_  384
#define E_  320000
#define DG_ 128
#define BN_ (B_*N_)
#define BE_ (B_*E_)

#define NW_      768
#define KPAD_    20480
#define TOTCH_PJ 640                   // 20480/32
#define NSPLIT_PJ 12                   // uneven ranges, 288 CTAs = one wave
#define STG_A    10240                 // 128*40*2
#define STG_B    8704                  // 32*136*2
#define STG_SZ   (STG_A+STG_B)         // 18944
#define SMEM_MMA (4*STG_SZ)            // 75776

// ---------------- device scratch ----------------
__device__ __align__(16) __half g_Y2[512*NW_];                 // fp16 single
__device__ __align__(16) __half g_Wq2[(size_t)N_*512];         // fp16 single
__device__ __align__(16) __half g_Wp2[(size_t)S_*KPAD_];       // fp16 single, zero-padded
__device__ __align__(16) __half g_gat2[(size_t)KPAD_*NW_];     // fp16 single; pad rows stay 0
__device__ __align__(16) __half g_xp[(size_t)BN_*F_];          // fp16
__device__ float g_uvw[3*F_];
__device__ float g_asrc[BN_*H_];
__device__ float g_adst[BN_*H_];
__device__ int   g_off[BN_+1];
__device__ int   g_cnt[BN_];
__device__ int   g_cur[BN_];
__device__ int   g_esrc[BE_];
__device__ float g_tmp[B_*S_*F_];

__device__ __forceinline__ float lrelu(float x){ return x > 0.f ? x : 0.2f*x; }
__device__ __forceinline__ unsigned su(const void* p){
    return (unsigned)__cvta_generic_to_shared(p);
}
__device__ __forceinline__ void cpa16(unsigned dst, const void* src, bool pred){
    int sz = pred ? 16 : 0;
    asm volatile("cp.async.cg.shared.global [%0], [%1], 16, %2;\n"
                 :: "r"(dst), "l"(src), "r"(sz));
}
__device__ __forceinline__ void ldsm4(unsigned addr, unsigned &r0, unsigned &r1, unsigned &r2, unsigned &r3){
    asm volatile("ldmatrix.sync.aligned.m8n8.x4.shared.b16 {%0,%1,%2,%3}, [%4];\n"
                 : "=r"(r0),"=r"(r1),"=r"(r2),"=r"(r3) : "r"(addr));
}
__device__ __forceinline__ void ldsm4t(unsigned addr, unsigned &r0, unsigned &r1, unsigned &r2, unsigned &r3){
    asm volatile("ldmatrix.sync.aligned.m8n8.x4.trans.shared.b16 {%0,%1,%2,%3}, [%4];\n"
                 : "=r"(r0),"=r"(r1),"=r"(r2),"=r"(r3) : "r"(addr));
}
__device__ __forceinline__ void mma16816(float* c, const unsigned* a, const unsigned* b){
    asm volatile("mma.sync.aligned.m16n8k16.row.col.f32.f16.f16.f32 "
                 "{%0,%1,%2,%3},{%4,%5,%6,%7},{%8,%9},{%0,%1,%2,%3};\n"
                 : "+f"(c[0]),"+f"(c[1]),"+f"(c[2]),"+f"(c[3])
                 : "r"(a[0]),"r"(a[1]),"r"(a[2]),"r"(a[3]),"r"(b[0]),"r"(b[1]));
}

// ---------------- mega setup: uvw + zero + tmpinit + Wq cvt + Wproj cvt ----------------
#define CVTWQ_T (N_*(S_/4))            // 2,560,000
#define CVTWP_T (S_*(KPAD_/4))         // 2,621,440
__global__ void k_setup(const float* __restrict__ Wlin, const float* __restrict__ Wm,
                        const float* __restrict__ bm, const float* __restrict__ bproj,
                        const float* __restrict__ Wq, const float* __restrict__ Wproj){
    int i = blockIdx.x*blockDim.x + threadIdx.x;
    if (i < F_){
        float u=0.f, v=0.f, w=0.f;
        for (int d = 0; d < D_; d++){
            float wl = Wlin[i*D_ + d];
            u += wl*Wm[d]; v += wl*bm[d]; w += wl;
        }
        g_uvw[i]=u; g_uvw[F_+i]=v; g_uvw[2*F_+i]=w;
    }
    if (i < BN_){ g_cnt[i] = 0; g_cur[i] = 0; }
    if (i < BN_*H_){ g_asrc[i] = 0.f; g_adst[i] = 0.f; }
    if (i < B_*S_*F_) g_tmp[i] = bproj[(i / F_) % S_];
    if (i < CVTWQ_T){
        int m = i >> 7, k = (i & 127) << 2;
        float4 x = *(const float4*)(Wq + (size_t)m*S_ + k);
        union { __half b[4]; uint2 u; } hh;
        hh.b[0] = __float2half_rn(x.x);
        hh.b[1] = __float2half_rn(x.y);
        hh.b[2] = __float2half_rn(x.z);
        hh.b[3] = __float2half_rn(x.w);
        *(uint2*)&g_Wq2[(size_t)m*512 + k] = hh.u;
    }
    if (i < CVTWP_T){
        int m = i / (KPAD_/4), k = (i % (KPAD_/4)) << 2;
        float4 x = (k < N_) ? *(const float4*)(Wproj + (size_t)m*N_ + k)
                            : make_float4(0.f,0.f,0.f,0.f);
        union { __half b[4]; uint2 u; } hh;
        hh.b[0] = __float2half_rn(x.x);
        hh.b[1] = __float2half_rn(x.y);
        hh.b[2] = __float2half_rn(x.z);
        hh.b[3] = __float2half_rn(x.w);
        *(uint2*)&g_Wp2[(size_t)m*KPAD_ + k] = hh.u;
    }
}

// ---------------- fp32 tiled GEMM (small), C = A @ Bm^T ----------------
__global__ void k_gemm_bt(const float* __restrict__ A, int strideA,
                          const float* __restrict__ Bm,
                          float* __restrict__ C, int strideC,
                          int K, int Ncol, const float* __restrict__ bias_col,
                          __half* __restrict__ Ysplit){
    const float* Ab = A + blockIdx.z * strideA;
    int m0 = blockIdx.y*64, n0 = blockIdx.x*64;
    __shared__ float As[16][64];
    __shared__ float Bs[16][64];
    int tid = threadIdx.x;
    int tm = tid >> 4, tn = tid & 15;
    int lrow = tid >> 2, lcol = (tid & 3)*4;
    float acc[4][4] = {};
    for (int k0 = 0; k0 < K; k0 += 16){
        float4 av = *(const float4*)(Ab + (m0+lrow)*K + k0 + lcol);
        As[lcol+0][lrow]=av.x; As[lcol+1][lrow]=av.y; As[lcol+2][lrow]=av.z; As[lcol+3][lrow]=av.w;
        float4 bv = *(const float4*)(Bm + (n0+lrow)*K + k0 + lcol);
        Bs[lcol+0][lrow]=bv.x; Bs[lcol+1][lrow]=bv.y; Bs[lcol+2][lrow]=bv.z; Bs[lcol+3][lrow]=bv.w;
        __syncthreads();
        #pragma unroll
        for (int kk = 0; kk < 16; kk++){
            float4 a4 = *(const float4*)&As[kk][tm*4];
            float4 b4 = *(const float4*)&Bs[kk][tn*4];
            float ar[4]={a4.x,a4.y,a4.z,a4.w}, br[4]={b4.x,b4.y,b4.z,b4.w};
            #pragma unroll
            for (int i=0;i<4;i++)
                #pragma unroll
                for (int j=0;j<4;j++) acc[i][j]=fmaf(ar[i],br[j],acc[i][j]);
        }
        __syncthreads();
    }
    #pragma unroll
    for (int i=0;i<4;i++){
        int row = m0 + tm*4 + i;
        #pragma unroll
        for (int j=0;j<4;j++){
            int col = n0 + tn*4 + j;
            float v = acc[i][j];
            if (Ysplit){
                int gc = blockIdx.z*384 + col;
                Ysplit[(size_t)row*NW_ + gc] = __float2half_rn(v);
            } else {
                v += bias_col[col];
                (C + blockIdx.z*strideC)[row*Ncol + col] = v;
            }
        }
    }
}

// ---------------- fp16 mma.sync GEMM, 128x128 CTA, 64x64 warps, 4-stage, frag dbuf ----
// EPI=0: xp epilogue (fused affine + fused attention partial dots via atomics)
// EPI=1: proj epilogue (atomicAdd -> g_tmp); uneven K-splits via totch/nsplit
template<int EPI>
__global__ __launch_bounds__(128, 2)
void k_mma(const __half* __restrict__ A, int lda, int M,
           const __half* __restrict__ Bm,
           int totch, int nsplit,
           const float* __restrict__ bq, const float* __restrict__ mask,
           const float* __restrict__ att_src, const float* __restrict__ att_dst)
{
    extern __shared__ __align__(16) char smem[];
    uint32_t sbase = su(smem);

    const int tid = threadIdx.x, lane = tid & 31, wid = tid >> 5;
    const int wm = wid & 1, wn = wid >> 1;
    const int m0 = blockIdx.y*128, n0 = blockIdx.x*128;
    const int cbeg = (blockIdx.z * totch) / nsplit;
    const int cend = ((blockIdx.z + 1) * totch) / nsplit;
    const int nchunks = cend - cbeg;
    const int kbeg = cbeg * 32;
    const int lrow = lane & 15, lhi = lane >> 4;

    auto load_stage = [&](int s, int c){
        int kv = kbeg + c*32;
        uint32_t ab = sbase + s*STG_SZ;
        uint32_t bb = ab + STG_A;
        #pragma unroll
        for (int i = tid; i < 512; i += 128){
            int row = i >> 2, seg = i & 3;
            int gr = m0 + row;
            const void* src = A + (size_t)(gr < M ? gr : M-1)*lda + kv + seg*8;
            cpa16(ab + (uint32_t)(row*80 + seg*16), src, gr < M);
        }
        #pragma unroll
        for (int i = tid; i < 512; i += 128){
            int row = i >> 4, seg = i & 15;
            const void* src = Bm + (size_t)(kv + row)*NW_ + n0 + seg*8;
            cpa16(bb + (uint32_t)(row*272 + seg*16), src, true);
        }
    };

    unsigned afr[2][4][4], bfr[2][8][2];
    auto ldfr = [&](int s, int kk, int buf){
        uint32_t ab = sbase + s*STG_SZ;
        uint32_t bb = ab + STG_A;
        int k0 = kk*16;
        #pragma unroll
        for (int mi = 0; mi < 4; ++mi){
            unsigned addr = ab + (uint32_t)((wm*64 + mi*16 + lrow)*80 + (k0 + lhi*8)*2);
            ldsm4(addr, afr[buf][mi][0], afr[buf][mi][1], afr[buf][mi][2], afr[buf][mi][3]);
        }
        #pragma unroll
        for (int nt = 0; nt < 4; ++nt){
            unsigned addr = bb + (uint32_t)((k0 + lrow)*272 + (wn*64 + nt*16 + lhi*8)*2);
            unsigned r0,r1,r2,r3;
            ldsm4t(addr, r0,r1,r2,r3);
            bfr[buf][nt*2  ][0]=r0; bfr[buf][nt*2  ][1]=r1;
            bfr[buf][nt*2+1][0]=r2; bfr[buf][nt*2+1][1]=r3;
        }
    };

    float acc[4][8][4] = {};

    #pragma unroll
    for (int s = 0; s < 3; s++){
        load_stage(s, s);
        asm volatile("cp.async.commit_group;");
    }
    asm volatile("cp.async.wait_group 2;");
    __syncthreads();
    ldfr(0, 0, 0);

    for (int c = 0; c < nchunks; ++c){
        int s = c & 3;
        ldfr(s, 1, 1);
        #pragma unroll
        for (int mi = 0; mi < 4; ++mi)
            #pragma unroll
            for (int ni = 0; ni < 8; ++ni)
                mma16816(acc[mi][ni], afr[0][mi], bfr[0][ni]);
        if (c + 3 < nchunks) load_stage((c+3)&3, c+3);
        asm volatile("cp.async.commit_group;");
        if (c + 1 < nchunks){
            asm volatile("cp.async.wait_group 2;");
            __syncthreads();
            ldfr((c+1)&3, 0, 0);
        }
        #pragma unroll
        for (int mi = 0; mi < 4; ++mi)
            #pragma unroll
            for (int ni = 0; ni < 8; ++ni)
                mma16816(acc[mi][ni], afr[1][mi], bfr[1][ni]);
    }

    // epilogue
    int g = lane >> 2, tig = lane & 3;
    const int bb2 = n0 >= 384;             // whole 128-col block is one (batch, head)
    const int hb  = (n0 - bb2*384) >> 7;
    #pragma unroll
    for (int mi = 0; mi < 4; ++mi){
        #pragma unroll
        for (int half = 0; half < 2; ++half){
            int row = m0 + wm*64 + mi*16 + g + half*8;
            if (row >= M) continue;
            if constexpr (EPI == 0){
                float bqv = bq[row];
                float mv  = mask[bb2*N_ + row];
                float s1 = 0.f, s2 = 0.f;
                #pragma unroll
                for (int ni = 0; ni < 8; ++ni){
                    int c = wn*64 + ni*8 + tig*2;
                    int f = hb*128 + c;
                    float v0 = acc[mi][ni][half*2+0]
                             + bqv*g_uvw[2*F_+f]   + mv*g_uvw[f]   + g_uvw[F_+f];
                    float v1 = acc[mi][ni][half*2+1]
                             + bqv*g_uvw[2*F_+f+1] + mv*g_uvw[f+1] + g_uvw[F_+f+1];
                    *(__half2*)&g_xp[((size_t)bb2*N_ + row)*F_ + f] = __floats2half2_rn(v0, v1);
                    s1 = fmaf(v0, att_src[hb*C_+c], fmaf(v1, att_src[hb*C_+c+1], s1));
                    s2 = fmaf(v0, att_dst[hb*C_+c], fmaf(v1, att_dst[hb*C_+c+1], s2));
                }
                s1 += __shfl_xor_sync(0xffffffffu, s1, 1);
                s1 += __shfl_xor_sync(0xffffffffu, s1, 2);
                s2 += __shfl_xor_sync(0xffffffffu, s2, 1);
                s2 += __shfl_xor_sync(0xffffffffu, s2, 2);
                if (tig == 0){
                    atomicAdd(&g_asrc[((size_t)bb2*N_ + row)*3 + hb], s1);
                    atomicAdd(&g_adst[((size_t)bb2*N_ + row)*3 + hb], s2);
                }
            } else {
                #pragma unroll
                for (int ni = 0; ni < 8; ++ni){
                    int c = wn*64 + ni*8 + tig*2;
                    int f = hb*128 + c;
                    float* dst = &g_tmp[((size_t)bb2*S_ + row)*F_ + f];
                    atomicAdd(&dst[0], acc[mi][ni][half*2+0]);
                    atomicAdd(&dst[1], acc[mi][ni][half*2+1]);
                }
            }
        }
    }
}

// ---------------- CSR ----------------
__global__ void k_count(const int* __restrict__ ei){
    int e = blockIdx.x*blockDim.x + threadIdx.x;
    if (e >= BE_) return;
    int b = e / E_, j = e - b*E_;
    atomicAdd(&g_cnt[ei[E_ + j] + b*N_], 1);
}
__global__ void k_scan(){
    __shared__ int ssum[1024];
    int tid = threadIdx.x;
    const int CH = (BN_ + 1023)/1024;
    int base = tid*CH, s = 0;
    for (int i = 0; i < CH; i++){ int idx = base+i; if (idx < BN_) s += g_cnt[idx]; }
    ssum[tid] = s;
    __syncthreads();
    for (int off = 1; off < 1024; off <<= 1){
        int v = (tid >= off) ? ssum[tid-off] : 0;
        __syncthreads();
        ssum[tid] += v;
        __syncthreads();
    }
    int run = ssum[tid] - s;
    for (int i = 0; i < CH; i++){
        int idx = base+i;
        if (idx < BN_){ g_off[idx] = run; run += g_cnt[idx]; }
    }
    if (tid == 1023) g_off[BN_] = ssum[1023];
}
__global__ void k_scatter(const int* __restrict__ ei){
    int e = blockIdx.x*blockDim.x + threadIdx.x;
    if (e >= BE_) return;
    int b = e / E_, j = e - b*E_;
    int src = ei[j] + b*N_;
    int dst = ei[E_ + j] + b*N_;
    int pos = g_off[dst] + atomicAdd(&g_cur[dst], 1);
    g_esrc[pos] = src;
}

// ---------------- fused aggregation: one edge pass, inline softmax denom, x2 unroll ----
__global__ void k_aggregate(const float* __restrict__ bias_gat){
    int n = blockIdx.x;
    int tid = threadIdx.x;      // 0..95, covers cols [tid*4, tid*4+4)
    int h = tid >> 5;
    int beg = g_off[n], end = g_off[n+1];
    float ad = g_adst[n*3+h];
    const uint2* xp2 = (const uint2*)g_xp;    // 4 halves per uint2, 96 per row
    float4 acc = make_float4(0.f,0.f,0.f,0.f);
    float den = 0.f;
    int i = beg;
    for (; i + 2 <= end; i += 2){
        int s0 = g_esrc[i], s1 = g_esrc[i+1];
        float as0 = g_asrc[s0*3+h];
        float as1 = g_asrc[s1*3+h];
        uint2 r0 = xp2[(size_t)s0*96 + tid];
        uint2 r1 = xp2[(size_t)s1*96 + tid];
        float a0 = __expf(lrelu(as0 + ad));
        float a1 = __expf(lrelu(as1 + ad));
        float2 v00 = __half22float2(*(const __half2*)&r0.x);
        float2 v01 = __half22float2(*(const __half2*)&r0.y);
        float2 v10 = __half22float2(*(const __half2*)&r1.x);
        float2 v11 = __half22float2(*(const __half2*)&r1.y);
        acc.x = fmaf(v00.x, a0, acc.x); acc.y = fmaf(v00.y, a0, acc.y);
        acc.z = fmaf(v01.x, a0, acc.z); acc.w = fmaf(v01.y, a0, acc.w);
        acc.x = fmaf(v10.x, a1, acc.x); acc.y = fmaf(v10.y, a1, acc.y);
        acc.z = fmaf(v11.x, a1, acc.z); acc.w = fmaf(v11.y, a1, acc.w);
        den += a0 + a1;
    }
    if (i < end){
        int s0 = g_esrc[i];
        float a0 = __expf(lrelu(g_asrc[s0*3+h] + ad));
        uint2 r0 = xp2[(size_t)s0*96 + tid];
        float2 v00 = __half22float2(*(const __half2*)&r0.x);
        float2 v01 = __half22float2(*(const __half2*)&r0.y);
        acc.x = fmaf(v00.x, a0, acc.x); acc.y = fmaf(v00.y, a0, acc.y);
        acc.z = fmaf(v01.x, a0, acc.z); acc.w = fmaf(v01.y, a0, acc.w);
        den += a0;
    }
    // self-loop
    {
        float als = __expf(lrelu(g_asrc[n*3+h] + ad));
        uint2 raw = xp2[(size_t)n*96 + tid];
        float2 v0 = __half22float2(*(const __half2*)&raw.x);
        float2 v1 = __half22float2(*(const __half2*)&raw.y);
        acc.x = fmaf(v0.x, als, acc.x); acc.y = fmaf(v0.y, als, acc.y);
        acc.z = fmaf(v1.x, als, acc.z); acc.w = fmaf(v1.y, als, acc.w);
        den += als;
    }
    float rd = 1.f/den;
    float4 bg = ((const float4*)bias_gat)[tid];
    float o0 = fmaf(acc.x, rd, bg.x);
    float o1 = fmaf(acc.y, rd, bg.y);
    float o2 = fmaf(acc.z, rd, bg.z);
    float o3 = fmaf(acc.w, rd, bg.w);

    int b = n / N_;
    int k = n - b*N_;
    int col = b*384 + tid*4;
    union { __half bv[4]; uint2 u; } hh;
    hh.bv[0] = __float2half_rn(o0);
    hh.bv[1] = __float2half_rn(o1);
    hh.bv[2] = __float2half_rn(o2);
    hh.bv[3] = __float2half_rn(o3);
    *(uint2*)&g_gat2[(size_t)k*NW_ + col] = hh.u;
}

// ---------------- host ----------------
extern "C" void kernel_launch(void* const* d_in, const int* in_sizes, int n_in,
                              void* d_out, int out_size){
    const float* x_enc    = (const float*)d_in[0];
    const float* mask     = (const float*)d_in[1];
    const int*   ei       = (const int*)  d_in[2];
    const float* Wq       = (const float*)d_in[3];
    const float* bq       = (const float*)d_in[4];
    const float* Wm       = (const float*)d_in[5];
    const float* bm       = (const float*)d_in[6];
    const float* Wlin     = (const float*)d_in[7];
    const float* att_src  = (const float*)d_in[8];
    const float* att_dst  = (const float*)d_in[9];
    const float* bias_gat = (const float*)d_in[10];
    const float* Wproj    = (const float*)d_in[11];
    const float* bproj    = (const float*)d_in[12];
    const float* Wtemp    = (const float*)d_in[13];
    const float* btemp    = (const float*)d_in[14];
    float* out = (float*)d_out;

    void *pY2=0, *pWq2=0, *pWp2=0, *pG2=0, *pTmp=0;
    cudaGetSymbolAddress(&pY2,  g_Y2);
    cudaGetSymbolAddress(&pWq2, g_Wq2);
    cudaGetSymbolAddress(&pWp2, g_Wp2);
    cudaGetSymbolAddress(&pG2,  g_gat2);
    cudaGetSymbolAddress(&pTmp, g_tmp);

    cudaFuncSetAttribute(k_mma<0>, cudaFuncAttributeMaxDynamicSharedMemorySize, SMEM_MMA);
    cudaFuncSetAttribute(k_mma<1>, cudaFuncAttributeMaxDynamicSharedMemorySize, SMEM_MMA);

    // 1) mega setup: uvw, cnt/cur, asrc/adst zero, tmp init, Wq cvt, Wproj cvt
    k_setup<<<(CVTWP_T + 255)/256, 256>>>(Wlin, Wm, bm, bproj, Wq, Wproj);
    // 2) Y = x_enc @ Wlin^T -> fp16
    k_gemm_bt<<<dim3(F_/64, S_/64, B_), 256>>>(
        x_enc, S_*D_, Wlin, nullptr, 0, D_, F_, nullptr, (__half*)pY2);
    // 3) xp GEMM + fused affine + fused attention dots
    k_mma<0><<<dim3(NW_/128, (N_ + 127)/128, 1), 128, SMEM_MMA>>>(
        (const __half*)pWq2, 512, N_,
        (const __half*)pY2,
        16, 1, bq, mask, att_src, att_dst);

    // CSR build
    k_count<<<(BE_ + 255)/256, 256>>>(ei);
    k_scan<<<1, 1024>>>();
    k_scatter<<<(BE_ + 255)/256, 256>>>(ei);

    // aggregation (fused softmax)
    k_aggregate<<<BN_, 96>>>(bias_gat);

    // proj
    k_mma<1><<<dim3(NW_/128, S_/128, NSPLIT_PJ), 128, SMEM_MMA>>>(
        (const __half*)pWp2, KPAD_, S_,
        (const __half*)pG2,
        TOTCH_PJ, NSPLIT_PJ, nullptr, nullptr, nullptr, nullptr);

    // final out
    k_gemm_bt<<<dim3(DG_/64, (B_*S_)/64, 1), 256>>>(
        (const float*)pTmp, 0, Wtemp, out, 0, F_, DG_, btemp, nullptr);
}

// round 15
// speedup vs baseline: 1.3652x; 1.0535x over previous
#include <cuda_runtime.h>
#include <cuda_fp16.h>
#include <math.h>
#include <stdint.h>

#define B_  2
#define S_  512
#define N_  20000
#define D_  384
#define H_  3
#define C_  128
#define F_  384
#define E_  320000
#define DG_ 128
#define BN_ (B_*N_)
#define BE_ (B_*E_)

#define NW_      768
#define KPAD_    20480
#define TOTCH_PJ 640                   // 20480/32
#define NSPLIT_PJ 12                   // uneven ranges, 288 CTAs = one wave
#define STG_A    10240                 // 128*40*2
#define STG_B    8704                  // 32*136*2
#define STG_SZ   (STG_A+STG_B)         // 18944
#define SMEM_MMA (4*STG_SZ)            // 75776

// ---------------- device scratch ----------------
__device__ __align__(16) __half g_Y2[512*NW_];                 // fp16 single
__device__ __align__(16) __half g_Wq2[(size_t)N_*512];         // fp16 single
__device__ __align__(16) __half g_Wp2[(size_t)S_*KPAD_];       // fp16 single, zero-padded
__device__ __align__(16) __half g_gat2[(size_t)KPAD_*NW_];     // fp16 single; pad rows stay 0
__device__ __align__(16) __half g_xp[(size_t)BN_*F_];          // fp16
__device__ float g_uvw[3*F_];
__device__ float g_asrc[BN_*H_];
__device__ float g_adst[BN_*H_];
__device__ int   g_off[BN_+1];
__device__ int   g_cnt[BN_];
__device__ int   g_cur[BN_];
__device__ int   g_esrc[BE_];
__device__ float g_tmp[B_*S_*F_];

__device__ __forceinline__ float lrelu(float x){ return x > 0.f ? x : 0.2f*x; }
__device__ __forceinline__ unsigned su(const void* p){
    return (unsigned)__cvta_generic_to_shared(p);
}
__device__ __forceinline__ void cpa16(unsigned dst, const void* src, bool pred){
    int sz = pred ? 16 : 0;
    asm volatile("cp.async.cg.shared.global [%0], [%1], 16, %2;\n"
                 :: "r"(dst), "l"(src), "r"(sz));
}
__device__ __forceinline__ void ldsm4(unsigned addr, unsigned &r0, unsigned &r1, unsigned &r2, unsigned &r3){
    asm volatile("ldmatrix.sync.aligned.m8n8.x4.shared.b16 {%0,%1,%2,%3}, [%4];\n"
                 : "=r"(r0),"=r"(r1),"=r"(r2),"=r"(r3) : "r"(addr));
}
__device__ __forceinline__ void ldsm4t(unsigned addr, unsigned &r0, unsigned &r1, unsigned &r2, unsigned &r3){
    asm volatile("ldmatrix.sync.aligned.m8n8.x4.trans.shared.b16 {%0,%1,%2,%3}, [%4];\n"
                 : "=r"(r0),"=r"(r1),"=r"(r2),"=r"(r3) : "r"(addr));
}
__device__ __forceinline__ void mma16816(float* c, const unsigned* a, const unsigned* b){
    asm volatile("mma.sync.aligned.m16n8k16.row.col.f32.f16.f16.f32 "
                 "{%0,%1,%2,%3},{%4,%5,%6,%7},{%8,%9},{%0,%1,%2,%3};\n"
                 : "+f"(c[0]),"+f"(c[1]),"+f"(c[2]),"+f"(c[3])
                 : "r"(a[0]),"r"(a[1]),"r"(a[2]),"r"(a[3]),"r"(b[0]),"r"(b[1]));
}

// ---------------- mega setup: uvw + zero + tmpinit + Wq cvt + Wproj cvt ----------------
#define CVTWQ_T (N_*(S_/4))            // 2,560,000
#define CVTWP_T (S_*(KPAD_/4))         // 2,621,440
__global__ void k_setup(const float* __restrict__ Wlin, const float* __restrict__ Wm,
                        const float* __restrict__ bm, const float* __restrict__ bproj,
                        const float* __restrict__ Wq, const float* __restrict__ Wproj){
    int i = blockIdx.x*blockDim.x + threadIdx.x;
    if (i < F_){
        float u=0.f, v=0.f, w=0.f;
        for (int d = 0; d < D_; d++){
            float wl = Wlin[i*D_ + d];
            u += wl*Wm[d]; v += wl*bm[d]; w += wl;
        }
        g_uvw[i]=u; g_uvw[F_+i]=v; g_uvw[2*F_+i]=w;
    }
    if (i < BN_){ g_cnt[i] = 0; g_cur[i] = 0; }
    if (i < BN_*H_){ g_asrc[i] = 0.f; g_adst[i] = 0.f; }
    if (i < B_*S_*F_) g_tmp[i] = bproj[(i / F_) % S_];
    if (i < CVTWQ_T){
        int m = i >> 7, k = (i & 127) << 2;
        float4 x = *(const float4*)(Wq + (size_t)m*S_ + k);
        union { __half b[4]; uint2 u; } hh;
        hh.b[0] = __float2half_rn(x.x);
        hh.b[1] = __float2half_rn(x.y);
        hh.b[2] = __float2half_rn(x.z);
        hh.b[3] = __float2half_rn(x.w);
        *(uint2*)&g_Wq2[(size_t)m*512 + k] = hh.u;
    }
    if (i < CVTWP_T){
        int m = i / (KPAD_/4), k = (i % (KPAD_/4)) << 2;
        float4 x = (k < N_) ? *(const float4*)(Wproj + (size_t)m*N_ + k)
                            : make_float4(0.f,0.f,0.f,0.f);
        union { __half b[4]; uint2 u; } hh;
        hh.b[0] = __float2half_rn(x.x);
        hh.b[1] = __float2half_rn(x.y);
        hh.b[2] = __float2half_rn(x.z);
        hh.b[3] = __float2half_rn(x.w);
        *(uint2*)&g_Wp2[(size_t)m*KPAD_ + k] = hh.u;
    }
}

// ---------------- fp32 tiled GEMM (small), C = A @ Bm^T ----------------
__global__ void k_gemm_bt(const float* __restrict__ A, int strideA,
                          const float* __restrict__ Bm,
                          float* __restrict__ C, int strideC,
                          int K, int Ncol, const float* __restrict__ bias_col,
                          __half* __restrict__ Ysplit){
    const float* Ab = A + blockIdx.z * strideA;
    int m0 = blockIdx.y*64, n0 = blockIdx.x*64;
    __shared__ float As[16][64];
    __shared__ float Bs[16][64];
    int tid = threadIdx.x;
    int tm = tid >> 4, tn = tid & 15;
    int lrow = tid >> 2, lcol = (tid & 3)*4;
    float acc[4][4] = {};
    for (int k0 = 0; k0 < K; k0 += 16){
        float4 av = *(const float4*)(Ab + (m0+lrow)*K + k0 + lcol);
        As[lcol+0][lrow]=av.x; As[lcol+1][lrow]=av.y; As[lcol+2][lrow]=av.z; As[lcol+3][lrow]=av.w;
        float4 bv = *(const float4*)(Bm + (n0+lrow)*K + k0 + lcol);
        Bs[lcol+0][lrow]=bv.x; Bs[lcol+1][lrow]=bv.y; Bs[lcol+2][lrow]=bv.z; Bs[lcol+3][lrow]=bv.w;
        __syncthreads();
        #pragma unroll
        for (int kk = 0; kk < 16; kk++){
            float4 a4 = *(const float4*)&As[kk][tm*4];
            float4 b4 = *(const float4*)&Bs[kk][tn*4];
            float ar[4]={a4.x,a4.y,a4.z,a4.w}, br[4]={b4.x,b4.y,b4.z,b4.w};
            #pragma unroll
            for (int i=0;i<4;i++)
                #pragma unroll
                for (int j=0;j<4;j++) acc[i][j]=fmaf(ar[i],br[j],acc[i][j]);
        }
        __syncthreads();
    }
    #pragma unroll
    for (int i=0;i<4;i++){
        int row = m0 + tm*4 + i;
        #pragma unroll
        for (int j=0;j<4;j++){
            int col = n0 + tn*4 + j;
            float v = acc[i][j];
            if (Ysplit){
                int gc = blockIdx.z*384 + col;
                Ysplit[(size_t)row*NW_ + gc] = __float2half_rn(v);
            } else {
                v += bias_col[col];
                (C + blockIdx.z*strideC)[row*Ncol + col] = v;
            }
        }
    }
}

// ---------------- fp16 mma.sync GEMM, 128x128 CTA, 64x64 warps, 4-stage, frag dbuf ----
// EPI=0: xp epilogue (fused affine + fused attention partial dots via atomics)
// EPI=1: proj epilogue (atomicAdd -> g_tmp); uneven K-splits via totch/nsplit
template<int EPI>
__global__ __launch_bounds__(128, 2)
void k_mma(const __half* __restrict__ A, int lda, int M,
           const __half* __restrict__ Bm,
           int totch, int nsplit,
           const float* __restrict__ bq, const float* __restrict__ mask,
           const float* __restrict__ att_src, const float* __restrict__ att_dst)
{
    extern __shared__ __align__(16) char smem[];
    uint32_t sbase = su(smem);

    const int tid = threadIdx.x, lane = tid & 31, wid = tid >> 5;
    const int wm = wid & 1, wn = wid >> 1;
    const int m0 = blockIdx.y*128, n0 = blockIdx.x*128;
    const int cbeg = (blockIdx.z * totch) / nsplit;
    const int cend = ((blockIdx.z + 1) * totch) / nsplit;
    const int nchunks = cend - cbeg;
    const int kbeg = cbeg * 32;
    const int lrow = lane & 15, lhi = lane >> 4;

    auto load_stage = [&](int s, int c){
        int kv = kbeg + c*32;
        uint32_t ab = sbase + s*STG_SZ;
        uint32_t bb = ab + STG_A;
        #pragma unroll
        for (int i = tid; i < 512; i += 128){
            int row = i >> 2, seg = i & 3;
            int gr = m0 + row;
            const void* src = A + (size_t)(gr < M ? gr : M-1)*lda + kv + seg*8;
            cpa16(ab + (uint32_t)(row*80 + seg*16), src, gr < M);
        }
        #pragma unroll
        for (int i = tid; i < 512; i += 128){
            int row = i >> 4, seg = i & 15;
            const void* src = Bm + (size_t)(kv + row)*NW_ + n0 + seg*8;
            cpa16(bb + (uint32_t)(row*272 + seg*16), src, true);
        }
    };

    unsigned afr[2][4][4], bfr[2][8][2];
    auto ldfr = [&](int s, int kk, int buf){
        uint32_t ab = sbase + s*STG_SZ;
        uint32_t bb = ab + STG_A;
        int k0 = kk*16;
        #pragma unroll
        for (int mi = 0; mi < 4; ++mi){
            unsigned addr = ab + (uint32_t)((wm*64 + mi*16 + lrow)*80 + (k0 + lhi*8)*2);
            ldsm4(addr, afr[buf][mi][0], afr[buf][mi][1], afr[buf][mi][2], afr[buf][mi][3]);
        }
        #pragma unroll
        for (int nt = 0; nt < 4; ++nt){
            unsigned addr = bb + (uint32_t)((k0 + lrow)*272 + (wn*64 + nt*16 + lhi*8)*2);
            unsigned r0,r1,r2,r3;
            ldsm4t(addr, r0,r1,r2,r3);
            bfr[buf][nt*2  ][0]=r0; bfr[buf][nt*2  ][1]=r1;
            bfr[buf][nt*2+1][0]=r2; bfr[buf][nt*2+1][1]=r3;
        }
    };

    float acc[4][8][4] = {};

    #pragma unroll
    for (int s = 0; s < 3; s++){
        load_stage(s, s);
        asm volatile("cp.async.commit_group;");
    }
    asm volatile("cp.async.wait_group 2;");
    __syncthreads();
    ldfr(0, 0, 0);

    for (int c = 0; c < nchunks; ++c){
        int s = c & 3;
        ldfr(s, 1, 1);
        #pragma unroll
        for (int mi = 0; mi < 4; ++mi)
            #pragma unroll
            for (int ni = 0; ni < 8; ++ni)
                mma16816(acc[mi][ni], afr[0][mi], bfr[0][ni]);
        if (c + 3 < nchunks) load_stage((c+3)&3, c+3);
        asm volatile("cp.async.commit_group;");
        if (c + 1 < nchunks){
            asm volatile("cp.async.wait_group 2;");
            __syncthreads();
            ldfr((c+1)&3, 0, 0);
        }
        #pragma unroll
        for (int mi = 0; mi < 4; ++mi)
            #pragma unroll
            for (int ni = 0; ni < 8; ++ni)
                mma16816(acc[mi][ni], afr[1][mi], bfr[1][ni]);
    }

    // epilogue
    int g = lane >> 2, tig = lane & 3;
    const int bb2 = n0 >= 384;             // whole 128-col block is one (batch, head)
    const int hb  = (n0 - bb2*384) >> 7;
    #pragma unroll
    for (int mi = 0; mi < 4; ++mi){
        #pragma unroll
        for (int half = 0; half < 2; ++half){
            int row = m0 + wm*64 + mi*16 + g + half*8;
            if (row >= M) continue;
            if constexpr (EPI == 0){
                float bqv = bq[row];
                float mv  = mask[bb2*N_ + row];
                float s1 = 0.f, s2 = 0.f;
                #pragma unroll
                for (int ni = 0; ni < 8; ++ni){
                    int c = wn*64 + ni*8 + tig*2;
                    int f = hb*128 + c;
                    float v0 = acc[mi][ni][half*2+0]
                             + bqv*g_uvw[2*F_+f]   + mv*g_uvw[f]   + g_uvw[F_+f];
                    float v1 = acc[mi][ni][half*2+1]
                             + bqv*g_uvw[2*F_+f+1] + mv*g_uvw[f+1] + g_uvw[F_+f+1];
                    *(__half2*)&g_xp[((size_t)bb2*N_ + row)*F_ + f] = __floats2half2_rn(v0, v1);
                    s1 = fmaf(v0, att_src[hb*C_+c], fmaf(v1, att_src[hb*C_+c+1], s1));
                    s2 = fmaf(v0, att_dst[hb*C_+c], fmaf(v1, att_dst[hb*C_+c+1], s2));
                }
                s1 += __shfl_xor_sync(0xffffffffu, s1, 1);
                s1 += __shfl_xor_sync(0xffffffffu, s1, 2);
                s2 += __shfl_xor_sync(0xffffffffu, s2, 1);
                s2 += __shfl_xor_sync(0xffffffffu, s2, 2);
                if (tig == 0){
                    atomicAdd(&g_asrc[((size_t)bb2*N_ + row)*3 + hb], s1);
                    atomicAdd(&g_adst[((size_t)bb2*N_ + row)*3 + hb], s2);
                }
            } else {
                #pragma unroll
                for (int ni = 0; ni < 8; ++ni){
                    int c = wn*64 + ni*8 + tig*2;
                    int f = hb*128 + c;
                    float* dst = &g_tmp[((size_t)bb2*S_ + row)*F_ + f];
                    atomicAdd(&dst[0], acc[mi][ni][half*2+0]);
                    atomicAdd(&dst[1], acc[mi][ni][half*2+1]);
                }
            }
        }
    }
}

// ---------------- CSR ----------------
__global__ void k_count(const int* __restrict__ ei){
    int e = blockIdx.x*blockDim.x + threadIdx.x;
    if (e >= BE_) return;
    int b = e / E_, j = e - b*E_;
    atomicAdd(&g_cnt[ei[E_ + j] + b*N_], 1);
}
__global__ void k_scan(){
    __shared__ int ssum[1024];
    int tid = threadIdx.x;
    const int CH = (BN_ + 1023)/1024;
    int base = tid*CH, s = 0;
    for (int i = 0; i < CH; i++){ int idx = base+i; if (idx < BN_) s += g_cnt[idx]; }
    ssum[tid] = s;
    __syncthreads();
    for (int off = 1; off < 1024; off <<= 1){
        int v = (tid >= off) ? ssum[tid-off] : 0;
        __syncthreads();
        ssum[tid] += v;
        __syncthreads();
    }
    int run = ssum[tid] - s;
    for (int i = 0; i < CH; i++){
        int idx = base+i;
        if (idx < BN_){ g_off[idx] = run; run += g_cnt[idx]; }
    }
    if (tid == 1023) g_off[BN_] = ssum[1023];
}
__global__ void k_scatter(const int* __restrict__ ei){
    int e = blockIdx.x*blockDim.x + threadIdx.x;
    if (e >= BE_) return;
    int b = e / E_, j = e - b*E_;
    int src = ei[j] + b*N_;
    int dst = ei[E_ + j] + b*N_;
    int pos = g_off[dst] + atomicAdd(&g_cur[dst], 1);
    g_esrc[pos] = src;
}

// ---------------- fused aggregation: warp-cooperative alpha (1 expf/edge/warp) ----------
__global__ void k_aggregate(const float* __restrict__ bias_gat){
    int n = blockIdx.x;
    int tid = threadIdx.x;      // 0..95, covers cols [tid*4, tid*4+4)
    int lane = tid & 31;
    int h = tid >> 5;
    int beg = g_off[n], end = g_off[n+1];
    float ad = g_adst[n*3+h];
    const uint2* xp2 = (const uint2*)g_xp;    // 4 halves per uint2, 96 per row
    float4 acc = make_float4(0.f,0.f,0.f,0.f);
    float den = 0.f;

    for (int base = beg; base < end; base += 32){
        int nn = end - base; if (nn > 32) nn = 32;
        // lane j computes (s, alpha) for edge base+j  -> 1 expf per edge per warp
        int   sL = 0;
        float aL = 0.f;
        if (lane < nn){
            sL = g_esrc[base + lane];
            aL = __expf(lrelu(g_asrc[sL*3 + h] + ad));
        }
        int j = 0;
        for (; j + 4 <= nn; j += 4){
            int   s0 = __shfl_sync(0xffffffffu, sL, j+0);
            int   s1 = __shfl_sync(0xffffffffu, sL, j+1);
            int   s2 = __shfl_sync(0xffffffffu, sL, j+2);
            int   s3 = __shfl_sync(0xffffffffu, sL, j+3);
            float a0 = __shfl_sync(0xffffffffu, aL, j+0);
            float a1 = __shfl_sync(0xffffffffu, aL, j+1);
            float a2 = __shfl_sync(0xffffffffu, aL, j+2);
            float a3 = __shfl_sync(0xffffffffu, aL, j+3);
            uint2 r0 = xp2[(size_t)s0*96 + tid];
            uint2 r1 = xp2[(size_t)s1*96 + tid];
            uint2 r2 = xp2[(size_t)s2*96 + tid];
            uint2 r3 = xp2[(size_t)s3*96 + tid];
            float2 v;
            v = __half22float2(*(const __half2*)&r0.x); acc.x=fmaf(v.x,a0,acc.x); acc.y=fmaf(v.y,a0,acc.y);
            v = __half22float2(*(const __half2*)&r0.y); acc.z=fmaf(v.x,a0,acc.z); acc.w=fmaf(v.y,a0,acc.w);
            v = __half22float2(*(const __half2*)&r1.x); acc.x=fmaf(v.x,a1,acc.x); acc.y=fmaf(v.y,a1,acc.y);
            v = __half22float2(*(const __half2*)&r1.y); acc.z=fmaf(v.x,a1,acc.z); acc.w=fmaf(v.y,a1,acc.w);
            v = __half22float2(*(const __half2*)&r2.x); acc.x=fmaf(v.x,a2,acc.x); acc.y=fmaf(v.y,a2,acc.y);
            v = __half22float2(*(const __half2*)&r2.y); acc.z=fmaf(v.x,a2,acc.z); acc.w=fmaf(v.y,a2,acc.w);
            v = __half22float2(*(const __half2*)&r3.x); acc.x=fmaf(v.x,a3,acc.x); acc.y=fmaf(v.y,a3,acc.y);
            v = __half22float2(*(const __half2*)&r3.y); acc.z=fmaf(v.x,a3,acc.z); acc.w=fmaf(v.y,a3,acc.w);
            den += a0 + a1 + a2 + a3;
        }
        for (; j < nn; ++j){
            int   s0 = __shfl_sync(0xffffffffu, sL, j);
            float a0 = __shfl_sync(0xffffffffu, aL, j);
            uint2 r0 = xp2[(size_t)s0*96 + tid];
            float2 v;
            v = __half22float2(*(const __half2*)&r0.x); acc.x=fmaf(v.x,a0,acc.x); acc.y=fmaf(v.y,a0,acc.y);
            v = __half22float2(*(const __half2*)&r0.y); acc.z=fmaf(v.x,a0,acc.z); acc.w=fmaf(v.y,a0,acc.w);
            den += a0;
        }
    }
    // self-loop
    {
        float als = __expf(lrelu(g_asrc[n*3+h] + ad));
        uint2 raw = xp2[(size_t)n*96 + tid];
        float2 v0 = __half22float2(*(const __half2*)&raw.x);
        float2 v1 = __half22float2(*(const __half2*)&raw.y);
        acc.x = fmaf(v0.x, als, acc.x); acc.y = fmaf(v0.y, als, acc.y);
        acc.z = fmaf(v1.x, als, acc.z); acc.w = fmaf(v1.y, als, acc.w);
        den += als;
    }
    float rd = 1.f/den;
    float4 bg = ((const float4*)bias_gat)[tid];
    float o0 = fmaf(acc.x, rd, bg.x);
    float o1 = fmaf(acc.y, rd, bg.y);
    float o2 = fmaf(acc.z, rd, bg.z);
    float o3 = fmaf(acc.w, rd, bg.w);

    int b = n / N_;
    int k = n - b*N_;
    int col = b*384 + tid*4;
    union { __half bv[4]; uint2 u; } hh;
    hh.bv[0] = __float2half_rn(o0);
    hh.bv[1] = __float2half_rn(o1);
    hh.bv[2] = __float2half_rn(o2);
    hh.bv[3] = __float2half_rn(o3);
    *(uint2*)&g_gat2[(size_t)k*NW_ + col] = hh.u;
}

// ---------------- host ----------------
extern "C" void kernel_launch(void* const* d_in, const int* in_sizes, int n_in,
                              void* d_out, int out_size){
    const float* x_enc    = (const float*)d_in[0];
    const float* mask     = (const float*)d_in[1];
    const int*   ei       = (const int*)  d_in[2];
    const float* Wq       = (const float*)d_in[3];
    const float* bq       = (const float*)d_in[4];
    const float* Wm       = (const float*)d_in[5];
    const float* bm       = (const float*)d_in[6];
    const float* Wlin     = (const float*)d_in[7];
    const float* att_src  = (const float*)d_in[8];
    const float* att_dst  = (const float*)d_in[9];
    const float* bias_gat = (const float*)d_in[10];
    const float* Wproj    = (const float*)d_in[11];
    const float* bproj    = (const float*)d_in[12];
    const float* Wtemp    = (const float*)d_in[13];
    const float* btemp    = (const float*)d_in[14];
    float* out = (float*)d_out;

    void *pY2=0, *pWq2=0, *pWp2=0, *pG2=0, *pTmp=0;
    cudaGetSymbolAddress(&pY2,  g_Y2);
    cudaGetSymbolAddress(&pWq2, g_Wq2);
    cudaGetSymbolAddress(&pWp2, g_Wp2);
    cudaGetSymbolAddress(&pG2,  g_gat2);
    cudaGetSymbolAddress(&pTmp, g_tmp);

    cudaFuncSetAttribute(k_mma<0>, cudaFuncAttributeMaxDynamicSharedMemorySize, SMEM_MMA);
    cudaFuncSetAttribute(k_mma<1>, cudaFuncAttributeMaxDynamicSharedMemorySize, SMEM_MMA);

    // 1) mega setup: uvw, cnt/cur, asrc/adst zero, tmp init, Wq cvt, Wproj cvt
    k_setup<<<(CVTWP_T + 255)/256, 256>>>(Wlin, Wm, bm, bproj, Wq, Wproj);
    // 2) Y = x_enc @ Wlin^T -> fp16
    k_gemm_bt<<<dim3(F_/64, S_/64, B_), 256>>>(
        x_enc, S_*D_, Wlin, nullptr, 0, D_, F_, nullptr, (__half*)pY2);
    // 3) xp GEMM + fused affine + fused attention dots
    k_mma<0><<<dim3(NW_/128, (N_ + 127)/128, 1), 128, SMEM_MMA>>>(
        (const __half*)pWq2, 512, N_,
        (const __half*)pY2,
        16, 1, bq, mask, att_src, att_dst);

    // CSR build
    k_count<<<(BE_ + 255)/256, 256>>>(ei);
    k_scan<<<1, 1024>>>();
    k_scatter<<<(BE_ + 255)/256, 256>>>(ei);

    // aggregation (fused softmax, warp-cooperative alpha)
    k_aggregate<<<BN_, 96>>>(bias_gat);

    // proj
    k_mma<1><<<dim3(NW_/128, S_/128, NSPLIT_PJ), 128, SMEM_MMA>>>(
        (const __half*)pWp2, KPAD_, S_,
        (const __half*)pG2,
        TOTCH_PJ, NSPLIT_PJ, nullptr, nullptr, nullptr, nullptr);

    // final out
    k_gemm_bt<<<dim3(DG_/64, (B_*S_)/64, 1), 256>>>(
        (const float*)pTmp, 0, Wtemp, out, 0, F_, DG_, btemp, nullptr);
}